// round 3
// baseline (speedup 1.0000x reference)
#include <cuda_runtime.h>
#include <math.h>
#include <stdint.h>

#define B_ 8
#define T_ 4096
#define D_ 768
#define DI_ 1536
#define M_ (B_*T_)          // 32768 rows
#define CB_ 256             // big chunk
#define NSTEP_ (T_/CB_)     // 16

// ---------------- scratch ---------------------------------------------------
__device__ float g_rms[M_];
__device__ float g_val[(size_t)M_*DI_];
__device__ float g_gate[(size_t)M_*DI_];
__device__ float g_out[(size_t)M_*D_];
__device__ float g_v[(size_t)M_*D_];
__device__ float g_reads[(size_t)M_*D_];
__device__ float g_W[2][(size_t)B_*D_*D_];
__device__ float g_P[(size_t)B_*NSTEP_*CB_*CB_];   // per-chunk masked S
__device__ float g_consts[2];                      // [0]=log(gamma), [1]=alpha

// ---------------- helpers ---------------------------------------------------
__device__ __forceinline__ uint32_t f2tf(float f) {
    uint32_t u;
    asm("cvt.rna.tf32.f32 %0, %1;" : "=r"(u) : "f"(f));
    return u;
}

__device__ __forceinline__ void mma8(float* c, const uint32_t* a, const uint32_t* b) {
    asm volatile(
        "mma.sync.aligned.m16n8k8.row.col.f32.tf32.tf32.f32 "
        "{%0,%1,%2,%3}, {%4,%5,%6,%7}, {%8,%9}, {%0,%1,%2,%3};"
        : "+f"(c[0]), "+f"(c[1]), "+f"(c[2]), "+f"(c[3])
        : "r"(a[0]), "r"(a[1]), "r"(a[2]), "r"(a[3]), "r"(b[0]), "r"(b[1]));
}

// 128x128 block, 8 warps as 4(m) x 2(n), warp tile 32x64. As/Bs: [16][136].
__device__ __forceinline__ void mma_block(
    const uint32_t (*As)[136], const uint32_t (*Bs)[136],
    float acc[2][8][4], int warp_m, int warp_n, int quad, int tq)
{
    #pragma unroll
    for (int ks = 0; ks < 2; ks++) {
        int kb = ks * 8;
        uint32_t af[2][4];
        #pragma unroll
        for (int mt = 0; mt < 2; mt++) {
            int m = warp_m * 32 + mt * 16 + quad;
            af[mt][0] = As[kb + tq][m];
            af[mt][1] = As[kb + tq][m + 8];
            af[mt][2] = As[kb + tq + 4][m];
            af[mt][3] = As[kb + tq + 4][m + 8];
        }
        #pragma unroll
        for (int nt = 0; nt < 8; nt++) {
            uint32_t bf[2];
            int n = warp_n * 64 + nt * 8 + quad;
            bf[0] = Bs[kb + tq][n];
            bf[1] = Bs[kb + tq + 4][n];
            #pragma unroll
            for (int mt = 0; mt < 2; mt++) mma8(acc[mt][nt], af[mt], bf);
        }
    }
}

// ---------------- small kernels ---------------------------------------------
__global__ void k_consts(const float* __restrict__ decay,
                         const float* __restrict__ log_alpha) {
    float g = 1.f / (1.f + expf(-decay[0]));
    g_consts[0] = logf(g);
    g_consts[1] = expf(log_alpha[0]);
}

__global__ void k_zeroW() {
    size_t i = (size_t)blockIdx.x * blockDim.x + threadIdx.x;
    if (i < (size_t)B_ * D_ * D_) g_W[0][i] = 0.f;
}

__global__ void k_rms(const float* __restrict__ x) {
    int warp = threadIdx.x >> 5, lane = threadIdx.x & 31;
    int row = blockIdx.x * 8 + warp;
    const float* p = x + (size_t)row * D_;
    float s = 0.f;
    #pragma unroll
    for (int i = lane; i < D_; i += 32) { float v = p[i]; s += v * v; }
    #pragma unroll
    for (int o = 16; o; o >>= 1) s += __shfl_xor_sync(0xffffffffu, s, o);
    if (lane == 0) g_rms[row] = rsqrtf(s * (1.f / D_) + 1e-5f);
}

// 8 timesteps per thread: causal depthwise conv(4) + silu, times silu'd gate
__global__ void k_conv(const float* __restrict__ cw, const float* __restrict__ cb) {
    int e = blockIdx.x * 256 + threadIdx.x;
    int t0 = blockIdx.y * 8;
    int b = blockIdx.z;
    size_t base = ((size_t)b * T_ + t0) * DI_ + e;
    float w0 = cw[e*4+0], w1 = cw[e*4+1], w2 = cw[e*4+2], w3 = cw[e*4+3];
    float bias = cb[e];
    float h0 = (t0 >= 3) ? g_val[base - 3*(size_t)DI_] : 0.f;
    float h1 = (t0 >= 2) ? g_val[base - 2*(size_t)DI_] : 0.f;
    float h2 = (t0 >= 1) ? g_val[base - 1*(size_t)DI_] : 0.f;
    #pragma unroll
    for (int j = 0; j < 8; j++) {
        size_t idx = base + (size_t)j * DI_;
        float cur = g_val[idx];
        float v = bias + w0*h0 + w1*h1 + w2*h2 + w3*cur;
        h0 = h1; h1 = h2; h2 = cur;
        float s = v / (1.f + __expf(-v));
        g_gate[idx] = s * g_gate[idx];
    }
}

// ---------------- pipelined TN GEMM (tf32) ----------------------------------
// C[m,n] = f(sum_k A[m,k]*B[n,k]); mode 0: acc ; 1: silu ; 2: add1+add2+alpha*acc
__global__ __launch_bounds__(256, 2) void k_gemm128(
    const float* __restrict__ A, const float* __restrict__ Bm,
    float* __restrict__ C, int N, int K,
    const float* __restrict__ rsA, const float* __restrict__ csA,
    int mode, const float* __restrict__ add1, const float* __restrict__ add2)
{
    __shared__ uint32_t As[2][16][136];
    __shared__ uint32_t Bs[2][16][136];
    int tid = threadIdx.x;
    int m0 = blockIdx.y * 128, n0 = blockIdx.x * 128;
    int warp = tid >> 5, lane = tid & 31;
    int warp_m = warp >> 1, warp_n = warp & 1;
    int quad = lane >> 2, tq = lane & 3;
    int r = tid >> 2, kc = (tid & 3) << 2;
    float acc[2][8][4] = {};

    float sc0 = rsA ? rsA[m0 + r]      : 1.f;
    float sc1 = rsA ? rsA[m0 + r + 64] : 1.f;
    float4 pa0, pa1, pb0, pb1, pcs;

    auto LOAD = [&](int k0) {
        pcs = csA ? *(const float4*)(csA + k0 + kc) : make_float4(1.f,1.f,1.f,1.f);
        pa0 = *(const float4*)(A  + (size_t)(m0 + r)      * K + k0 + kc);
        pa1 = *(const float4*)(A  + (size_t)(m0 + r + 64) * K + k0 + kc);
        pb0 = *(const float4*)(Bm + (size_t)(n0 + r)      * K + k0 + kc);
        pb1 = *(const float4*)(Bm + (size_t)(n0 + r + 64) * K + k0 + kc);
    };
    auto STORE = [&](int bf) {
        As[bf][kc+0][r]    = f2tf(pa0.x*sc0*pcs.x); As[bf][kc+1][r]    = f2tf(pa0.y*sc0*pcs.y);
        As[bf][kc+2][r]    = f2tf(pa0.z*sc0*pcs.z); As[bf][kc+3][r]    = f2tf(pa0.w*sc0*pcs.w);
        As[bf][kc+0][r+64] = f2tf(pa1.x*sc1*pcs.x); As[bf][kc+1][r+64] = f2tf(pa1.y*sc1*pcs.y);
        As[bf][kc+2][r+64] = f2tf(pa1.z*sc1*pcs.z); As[bf][kc+3][r+64] = f2tf(pa1.w*sc1*pcs.w);
        Bs[bf][kc+0][r]    = f2tf(pb0.x);           Bs[bf][kc+1][r]    = f2tf(pb0.y);
        Bs[bf][kc+2][r]    = f2tf(pb0.z);           Bs[bf][kc+3][r]    = f2tf(pb0.w);
        Bs[bf][kc+0][r+64] = f2tf(pb1.x);           Bs[bf][kc+1][r+64] = f2tf(pb1.y);
        Bs[bf][kc+2][r+64] = f2tf(pb1.z);           Bs[bf][kc+3][r+64] = f2tf(pb1.w);
    };

    LOAD(0); STORE(0);
    __syncthreads();
    int nk = K >> 4;
    for (int ki = 0; ki < nk; ki++) {
        int buf = ki & 1;
        if (ki + 1 < nk) LOAD((ki + 1) << 4);
        mma_block(As[buf], Bs[buf], acc, warp_m, warp_n, quad, tq);
        if (ki + 1 < nk) STORE(buf ^ 1);
        __syncthreads();
    }

    float alpha = (mode == 2) ? g_consts[1] : 0.f;
    #pragma unroll
    for (int mt = 0; mt < 2; mt++)
        #pragma unroll
        for (int h = 0; h < 2; h++) {
            int mi = m0 + warp_m * 32 + mt * 16 + quad + h * 8;
            size_t row = (size_t)mi * N;
            #pragma unroll
            for (int nt = 0; nt < 8; nt++) {
                int ni = n0 + warp_n * 64 + nt * 8 + tq * 2;
                float c0 = acc[mt][nt][h*2 + 0];
                float c1 = acc[mt][nt][h*2 + 1];
                if (mode == 1) {
                    c0 = c0 / (1.f + __expf(-c0));
                    c1 = c1 / (1.f + __expf(-c1));
                } else if (mode == 2) {
                    float2 a1 = *(const float2*)(add1 + row + ni);
                    float2 a2 = *(const float2*)(add2 + row + ni);
                    c0 = a1.x + a2.x + alpha * c0;
                    c1 = a1.y + a2.y + alpha * c1;
                }
                *(float2*)(C + row + ni) = make_float2(c0, c1);
            }
        }
}

// ---------------- batched pchunk: all chunks at once ------------------------
// P[s,b][i][j] = (i>j) ? (r_i . k_j) * gamma^(i-1-j) : 0 ;  k_j = out[t0+j-1]
__global__ __launch_bounds__(256, 2) void k_pchunk() {
    int zb = blockIdx.z; int s = zb >> 3; int b = zb & 7;
    int t0 = s * CB_;
    const float* A = g_out + ((size_t)b * T_ + t0) * D_;
    __shared__ uint32_t As[2][16][136];
    __shared__ uint32_t Bs[2][16][136];
    __shared__ float gpow[256];
    int tid = threadIdx.x;
    int m0 = blockIdx.y * 128, n0 = blockIdx.x * 128;
    int warp = tid >> 5, lane = tid & 31;
    int warp_m = warp >> 1, warp_n = warp & 1;
    int quad = lane >> 2, tq = lane & 3;
    int r = tid >> 2, kc = (tid & 3) << 2;
    float acc[2][8][4] = {};
    float lg = g_consts[0];
    gpow[tid] = __expf((float)tid * lg);

    float4 pa0, pa1, pb0, pb1;
    auto LOAD = [&](int k0) {
        pa0 = *(const float4*)(A + (size_t)(m0 + r)      * D_ + k0 + kc);
        pa1 = *(const float4*)(A + (size_t)(m0 + r + 64) * D_ + k0 + kc);
        int tok0 = t0 + n0 + r - 1;
        pb0 = (tok0 >= 0) ? *(const float4*)(g_out + ((size_t)b*T_ + tok0)*D_ + k0 + kc)
                          : make_float4(0.f,0.f,0.f,0.f);
        pb1 = *(const float4*)(g_out + ((size_t)b*T_ + tok0 + 64)*D_ + k0 + kc);
    };
    auto STORE = [&](int bf) {
        As[bf][kc+0][r]    = f2tf(pa0.x); As[bf][kc+1][r]    = f2tf(pa0.y);
        As[bf][kc+2][r]    = f2tf(pa0.z); As[bf][kc+3][r]    = f2tf(pa0.w);
        As[bf][kc+0][r+64] = f2tf(pa1.x); As[bf][kc+1][r+64] = f2tf(pa1.y);
        As[bf][kc+2][r+64] = f2tf(pa1.z); As[bf][kc+3][r+64] = f2tf(pa1.w);
        Bs[bf][kc+0][r]    = f2tf(pb0.x); Bs[bf][kc+1][r]    = f2tf(pb0.y);
        Bs[bf][kc+2][r]    = f2tf(pb0.z); Bs[bf][kc+3][r]    = f2tf(pb0.w);
        Bs[bf][kc+0][r+64] = f2tf(pb1.x); Bs[bf][kc+1][r+64] = f2tf(pb1.y);
        Bs[bf][kc+2][r+64] = f2tf(pb1.z); Bs[bf][kc+3][r+64] = f2tf(pb1.w);
    };

    LOAD(0); STORE(0);
    __syncthreads();
    int nk = D_ >> 4;
    for (int ki = 0; ki < nk; ki++) {
        int buf = ki & 1;
        if (ki + 1 < nk) LOAD((ki + 1) << 4);
        mma_block(As[buf], Bs[buf], acc, warp_m, warp_n, quad, tq);
        if (ki + 1 < nk) STORE(buf ^ 1);
        __syncthreads();
    }

    float* P = g_P + ((size_t)(s * B_ + b)) * CB_ * CB_;
    #pragma unroll
    for (int mt = 0; mt < 2; mt++)
        #pragma unroll
        for (int h = 0; h < 2; h++) {
            int ii = m0 + warp_m * 32 + mt * 16 + quad + h * 8;
            #pragma unroll
            for (int nt = 0; nt < 8; nt++) {
                int jj = n0 + warp_n * 64 + nt * 8 + tq * 2;
                float c0 = (ii > jj)     ? acc[mt][nt][h*2+0] * gpow[ii-1-jj] : 0.f;
                float c1 = (ii > jj + 1) ? acc[mt][nt][h*2+1] * gpow[ii-2-jj] : 0.f;
                *(float2*)(P + (size_t)ii * CB_ + jj) = make_float2(c0, c1);
            }
        }
}

// ---------------- batched intra: g_reads = P @ v ----------------------------
__global__ __launch_bounds__(256, 2) void k_intra() {
    int zb = blockIdx.z; int s = zb >> 3; int b = zb & 7;
    int t0 = s * CB_;
    const float* P = g_P + ((size_t)(s * B_ + b)) * CB_ * CB_;
    __shared__ uint32_t As[2][16][136];
    __shared__ uint32_t Bs[2][16][136];
    int tid = threadIdx.x;
    int m0 = blockIdx.y * 128, n0 = blockIdx.x * 128;   // m over CB, n over D
    int warp = tid >> 5, lane = tid & 31;
    int warp_m = warp >> 1, warp_n = warp & 1;
    int quad = lane >> 2, tq = lane & 3;
    int r = tid >> 2, kc = (tid & 3) << 2;
    int ki2 = tid >> 4, cc = (tid & 15) << 3;
    float acc[2][8][4] = {};

    float4 pa0, pa1, pb0, pb1;
    auto LOAD = [&](int k0) {
        pa0 = *(const float4*)(P + (size_t)(m0 + r)      * CB_ + k0 + kc);
        pa1 = *(const float4*)(P + (size_t)(m0 + r + 64) * CB_ + k0 + kc);
        const float* brow = g_v + ((size_t)b*T_ + t0 + k0 + ki2) * D_ + n0 + cc;
        pb0 = *(const float4*)(brow);
        pb1 = *(const float4*)(brow + 4);
    };
    auto STORE = [&](int bf) {
        As[bf][kc+0][r]    = f2tf(pa0.x); As[bf][kc+1][r]    = f2tf(pa0.y);
        As[bf][kc+2][r]    = f2tf(pa0.z); As[bf][kc+3][r]    = f2tf(pa0.w);
        As[bf][kc+0][r+64] = f2tf(pa1.x); As[bf][kc+1][r+64] = f2tf(pa1.y);
        As[bf][kc+2][r+64] = f2tf(pa1.z); As[bf][kc+3][r+64] = f2tf(pa1.w);
        Bs[bf][ki2][cc+0] = f2tf(pb0.x); Bs[bf][ki2][cc+1] = f2tf(pb0.y);
        Bs[bf][ki2][cc+2] = f2tf(pb0.z); Bs[bf][ki2][cc+3] = f2tf(pb0.w);
        Bs[bf][ki2][cc+4] = f2tf(pb1.x); Bs[bf][ki2][cc+5] = f2tf(pb1.y);
        Bs[bf][ki2][cc+6] = f2tf(pb1.z); Bs[bf][ki2][cc+7] = f2tf(pb1.w);
    };

    LOAD(0); STORE(0);
    __syncthreads();
    int nk = CB_ >> 4;
    for (int ki = 0; ki < nk; ki++) {
        int buf = ki & 1;
        if (ki + 1 < nk) LOAD((ki + 1) << 4);
        mma_block(As[buf], Bs[buf], acc, warp_m, warp_n, quad, tq);
        if (ki + 1 < nk) STORE(buf ^ 1);
        __syncthreads();
    }

    #pragma unroll
    for (int mt = 0; mt < 2; mt++)
        #pragma unroll
        for (int h = 0; h < 2; h++) {
            int mi = m0 + warp_m * 32 + mt * 16 + quad + h * 8;
            size_t row = ((size_t)b * T_ + t0 + mi) * D_;
            #pragma unroll
            for (int nt = 0; nt < 8; nt++) {
                int ni = n0 + warp_n * 64 + nt * 8 + tq * 2;
                *(float2*)(g_reads + row + ni) =
                    make_float2(acc[mt][nt][h*2+0], acc[mt][nt][h*2+1]);
            }
        }
}

// ---------------- merged sequential step ------------------------------------
// y<6:  Wn[d,e] = gamma^CB * Wc[d,e] + sum_i gw(i) v[i,d] k[i,e]
// y>=6: g_reads[i,d] += gamma^i * sum_e r[i,e] Wc[d,e]
__global__ __launch_bounds__(256, 2) void k_step(int t0,
        const float* __restrict__ Wc, float* __restrict__ Wn) {
    int b = blockIdx.z;
    __shared__ uint32_t As[2][16][136];
    __shared__ uint32_t Bs[2][16][136];
    int tid = threadIdx.x;
    int warp = tid >> 5, lane = tid & 31;
    int warp_m = warp >> 1, warp_n = warp & 1;
    int quad = lane >> 2, tq = lane & 3;
    int r = tid >> 2, kc = (tid & 3) << 2;
    int ki2 = tid >> 4, cc = (tid & 15) << 3;
    float lg = g_consts[0];
    float acc[2][8][4] = {};
    int n0 = blockIdx.x * 128;

    if (blockIdx.y < 6) {
        // ---- W update ----
        int m0 = blockIdx.y * 128;
        float4 pa0, pa1, pb0, pb1;
        auto LOAD = [&](int k0) {
            int i = k0 + ki2;
            float gw = __expf((float)(CB_ - 1 - i) * lg);
            const float* arow = g_v + ((size_t)b*T_ + t0 + i) * D_ + m0 + cc;
            pa0 = *(const float4*)(arow);
            pa1 = *(const float4*)(arow + 4);
            pa0.x *= gw; pa0.y *= gw; pa0.z *= gw; pa0.w *= gw;
            pa1.x *= gw; pa1.y *= gw; pa1.z *= gw; pa1.w *= gw;
            int tok = t0 + i - 1;
            if (tok >= 0) {
                const float* brow = g_out + ((size_t)b*T_ + tok) * D_ + n0 + cc;
                pb0 = *(const float4*)(brow);
                pb1 = *(const float4*)(brow + 4);
            } else {
                pb0 = make_float4(0.f,0.f,0.f,0.f); pb1 = pb0;
            }
        };
        auto STORE = [&](int bf) {
            As[bf][ki2][cc+0] = f2tf(pa0.x); As[bf][ki2][cc+1] = f2tf(pa0.y);
            As[bf][ki2][cc+2] = f2tf(pa0.z); As[bf][ki2][cc+3] = f2tf(pa0.w);
            As[bf][ki2][cc+4] = f2tf(pa1.x); As[bf][ki2][cc+5] = f2tf(pa1.y);
            As[bf][ki2][cc+6] = f2tf(pa1.z); As[bf][ki2][cc+7] = f2tf(pa1.w);
            Bs[bf][ki2][cc+0] = f2tf(pb0.x); Bs[bf][ki2][cc+1] = f2tf(pb0.y);
            Bs[bf][ki2][cc+2] = f2tf(pb0.z); Bs[bf][ki2][cc+3] = f2tf(pb0.w);
            Bs[bf][ki2][cc+4] = f2tf(pb1.x); Bs[bf][ki2][cc+5] = f2tf(pb1.y);
            Bs[bf][ki2][cc+6] = f2tf(pb1.z); Bs[bf][ki2][cc+7] = f2tf(pb1.w);
        };
        LOAD(0); STORE(0);
        __syncthreads();
        int nk = CB_ >> 4;
        for (int ki = 0; ki < nk; ki++) {
            int buf = ki & 1;
            if (ki + 1 < nk) LOAD((ki + 1) << 4);
            mma_block(As[buf], Bs[buf], acc, warp_m, warp_n, quad, tq);
            if (ki + 1 < nk) STORE(buf ^ 1);
            __syncthreads();
        }
        float gC = __expf((float)CB_ * lg);
        size_t base = (size_t)b * D_ * D_;
        #pragma unroll
        for (int mt = 0; mt < 2; mt++)
            #pragma unroll
            for (int h = 0; h < 2; h++) {
                int d = m0 + warp_m * 32 + mt * 16 + quad + h * 8;
                #pragma unroll
                for (int nt = 0; nt < 8; nt++) {
                    int e = n0 + warp_n * 64 + nt * 8 + tq * 2;
                    size_t idx = base + (size_t)d * D_ + e;
                    float2 w = *(const float2*)(Wc + idx);
                    *(float2*)(Wn + idx) = make_float2(gC*w.x + acc[mt][nt][h*2+0],
                                                       gC*w.y + acc[mt][nt][h*2+1]);
                }
            }
    } else {
        // ---- inter reads: accumulate into g_reads ----
        int m0 = (blockIdx.y - 6) * 128;
        const float* A  = g_out + ((size_t)b * T_ + t0) * D_;
        const float* Wb = Wc + (size_t)b * D_ * D_;
        float4 pa0, pa1, pb0, pb1;
        auto LOAD = [&](int k0) {
            pa0 = *(const float4*)(A  + (size_t)(m0 + r)      * D_ + k0 + kc);
            pa1 = *(const float4*)(A  + (size_t)(m0 + r + 64) * D_ + k0 + kc);
            pb0 = *(const float4*)(Wb + (size_t)(n0 + r)      * D_ + k0 + kc);
            pb1 = *(const float4*)(Wb + (size_t)(n0 + r + 64) * D_ + k0 + kc);
        };
        auto STORE = [&](int bf) {
            As[bf][kc+0][r]    = f2tf(pa0.x); As[bf][kc+1][r]    = f2tf(pa0.y);
            As[bf][kc+2][r]    = f2tf(pa0.z); As[bf][kc+3][r]    = f2tf(pa0.w);
            As[bf][kc+0][r+64] = f2tf(pa1.x); As[bf][kc+1][r+64] = f2tf(pa1.y);
            As[bf][kc+2][r+64] = f2tf(pa1.z); As[bf][kc+3][r+64] = f2tf(pa1.w);
            Bs[bf][kc+0][r]    = f2tf(pb0.x); Bs[bf][kc+1][r]    = f2tf(pb0.y);
            Bs[bf][kc+2][r]    = f2tf(pb0.z); Bs[bf][kc+3][r]    = f2tf(pb0.w);
            Bs[bf][kc+0][r+64] = f2tf(pb1.x); Bs[bf][kc+1][r+64] = f2tf(pb1.y);
            Bs[bf][kc+2][r+64] = f2tf(pb1.z); Bs[bf][kc+3][r+64] = f2tf(pb1.w);
        };
        LOAD(0); STORE(0);
        __syncthreads();
        int nk = D_ >> 4;
        for (int ki = 0; ki < nk; ki++) {
            int buf = ki & 1;
            if (ki + 1 < nk) LOAD((ki + 1) << 4);
            mma_block(As[buf], Bs[buf], acc, warp_m, warp_n, quad, tq);
            if (ki + 1 < nk) STORE(buf ^ 1);
            __syncthreads();
        }
        #pragma unroll
        for (int mt = 0; mt < 2; mt++)
            #pragma unroll
            for (int h = 0; h < 2; h++) {
                int mi = m0 + warp_m * 32 + mt * 16 + quad + h * 8;   // i in chunk
                float sc = __expf((float)mi * lg);
                size_t row = ((size_t)b * T_ + t0 + mi) * D_;
                #pragma unroll
                for (int nt = 0; nt < 8; nt++) {
                    int ni = n0 + warp_n * 64 + nt * 8 + tq * 2;
                    float2 old = *(const float2*)(g_reads + row + ni);
                    *(float2*)(g_reads + row + ni) =
                        make_float2(old.x + sc * acc[mt][nt][h*2+0],
                                    old.y + sc * acc[mt][nt][h*2+1]);
                }
            }
    }
}

// ---------------- launch ----------------------------------------------------
extern "C" void kernel_launch(void* const* d_in, const int* in_sizes, int n_in,
                              void* d_out, int out_size) {
    const float* x         = (const float*)d_in[0];
    const float* norm_w    = (const float*)d_in[1];
    const float* proj_w    = (const float*)d_in[2];
    const float* gate_w    = (const float*)d_in[3];
    const float* conv_w    = (const float*)d_in[4];
    const float* conv_b    = (const float*)d_in[5];
    const float* out_proj  = (const float*)d_in[6];
    const float* write_w   = (const float*)d_in[7];
    const float* read_w    = (const float*)d_in[8];
    const float* decay     = (const float*)d_in[9];
    const float* log_alpha = (const float*)d_in[10];
    float* out = (float*)d_out;

    float *p_rms, *p_val, *p_gate, *p_out, *p_v, *p_reads, *p_W;
    cudaGetSymbolAddress((void**)&p_rms,   g_rms);
    cudaGetSymbolAddress((void**)&p_val,   g_val);
    cudaGetSymbolAddress((void**)&p_gate,  g_gate);
    cudaGetSymbolAddress((void**)&p_out,   g_out);
    cudaGetSymbolAddress((void**)&p_v,     g_v);
    cudaGetSymbolAddress((void**)&p_reads, g_reads);
    cudaGetSymbolAddress((void**)&p_W,     g_W);
    float* p_W0 = p_W;
    float* p_W1 = p_W + (size_t)B_ * D_ * D_;

    k_consts<<<1, 1>>>(decay, log_alpha);
    k_rms<<<M_/8, 256>>>(x);

    k_gemm128<<<dim3(DI_/128, M_/128), 256>>>(x, proj_w, p_val, DI_, D_,
                                              p_rms, norm_w, 0, nullptr, nullptr);
    k_gemm128<<<dim3(DI_/128, M_/128), 256>>>(x, gate_w, p_gate, DI_, D_,
                                              p_rms, norm_w, 1, nullptr, nullptr);
    k_conv<<<dim3(DI_/256, T_/8, B_), 256>>>(conv_w, conv_b);
    k_gemm128<<<dim3(D_/128, M_/128), 256>>>(p_gate, out_proj, p_out, D_, DI_,
                                             nullptr, nullptr, 0, nullptr, nullptr);
    k_gemm128<<<dim3(D_/128, M_/128), 256>>>(p_out, write_w, p_v, D_, D_,
                                             nullptr, nullptr, 0, nullptr, nullptr);

    // batched chunk-local work (independent of W)
    k_pchunk<<<dim3(CB_/128, CB_/128, NSTEP_*B_), 256>>>();
    k_intra <<<dim3(D_/128,  CB_/128, NSTEP_*B_), 256>>>();

    // sequential state chain: wupdate + inter-reads merged per step
    k_zeroW<<<(int)(((size_t)B_*D_*D_ + 1023) / 1024), 1024>>>();
    const float* Wc = p_W0;
    float* Wn = p_W1;
    for (int s = 0; s < NSTEP_; s++) {
        k_step<<<dim3(D_/128, 8, B_), 256>>>(s * CB_, Wc, Wn);
        float* tmp = (float*)Wc; Wc = Wn; Wn = tmp;
    }

    // final: y = x + out + alpha * (reads @ read^T)
    k_gemm128<<<dim3(D_/128, M_/128), 256>>>(p_reads, read_w, out, D_, D_,
                                             nullptr, nullptr, 2, x, p_out);
}

// round 6
// speedup vs baseline: 1.7180x; 1.7180x over previous
#include <cuda_runtime.h>
#include <cuda_fp16.h>
#include <math.h>
#include <stdint.h>

#define B_ 8
#define T_ 4096
#define D_ 768
#define DI_ 1536
#define M_ (B_*T_)          // 32768 rows
#define CB_ 256             // big chunk
#define NSTEP_ (T_/CB_)     // 16
#define SH_ 40              // fp16 SMEM row stride (halfs), conflict-free padding

// ---------------- scratch ---------------------------------------------------
__device__ float g_xn[(size_t)M_*D_];
__device__ float g_val[(size_t)M_*DI_];
__device__ float g_gate[(size_t)M_*DI_];
__device__ float g_out[(size_t)M_*D_];
__device__ float g_v[(size_t)M_*D_];
__device__ float g_reads[(size_t)M_*D_];
__device__ float g_W[2][(size_t)B_*D_*D_];
__device__ float g_P[(size_t)B_*NSTEP_*CB_*CB_];
__device__ float g_consts[2];                // [0]=log(gamma), [1]=alpha

// ---------------- helpers ---------------------------------------------------
__device__ __forceinline__ uint32_t f2tf(float f) {
    uint32_t u;
    asm("cvt.rna.tf32.f32 %0, %1;" : "=r"(u) : "f"(f));
    return u;
}

__device__ __forceinline__ void st4h(__half* dst, float4 v) {
    __half2 lo = __floats2half2_rn(v.x, v.y);
    __half2 hi = __floats2half2_rn(v.z, v.w);
    uint2 u;
    u.x = *(uint32_t*)&lo;
    u.y = *(uint32_t*)&hi;
    *(uint2*)dst = u;
}

// ---- fp16 tensor core (m16n8k16), 128x128 block, 8 warps 4m x 2n ----------
__device__ __forceinline__ void mma_h(float* c, const uint32_t* a, const uint32_t* b) {
    asm volatile(
        "mma.sync.aligned.m16n8k16.row.col.f32.f16.f16.f32 "
        "{%0,%1,%2,%3}, {%4,%5,%6,%7}, {%8,%9}, {%0,%1,%2,%3};"
        : "+f"(c[0]), "+f"(c[1]), "+f"(c[2]), "+f"(c[3])
        : "r"(a[0]), "r"(a[1]), "r"(a[2]), "r"(a[3]), "r"(b[0]), "r"(b[1]));
}

// As/Bs: [128][SH_] halfs, row-major (k contiguous), covers BK=32 per call.
__device__ __forceinline__ void mma_block_h(
    const __half* As, const __half* Bs, float acc[2][8][4],
    int warp_m, int warp_n, int g, int tq)
{
    #pragma unroll
    for (int ks = 0; ks < 32; ks += 16) {
        uint32_t af[2][4];
        #pragma unroll
        for (int mt = 0; mt < 2; mt++) {
            const __half* p = As + (warp_m*32 + mt*16 + g)*SH_ + ks + tq*2;
            af[mt][0] = *(const uint32_t*)p;
            af[mt][1] = *(const uint32_t*)(p + 8*SH_);
            af[mt][2] = *(const uint32_t*)(p + 8);
            af[mt][3] = *(const uint32_t*)(p + 8*SH_ + 8);
        }
        #pragma unroll
        for (int nt = 0; nt < 8; nt++) {
            const __half* q = Bs + (warp_n*64 + nt*8 + g)*SH_ + ks + tq*2;
            uint32_t bf[2];
            bf[0] = *(const uint32_t*)q;
            bf[1] = *(const uint32_t*)(q + 8);
            mma_h(acc[0][nt], af[0], bf);
            mma_h(acc[1][nt], af[1], bf);
        }
    }
}

// ---- tf32 tensor core (m16n8k8) k-major core, for transpose-contraction ----
__device__ __forceinline__ void mma8(float* c, const uint32_t* a, const uint32_t* b) {
    asm volatile(
        "mma.sync.aligned.m16n8k8.row.col.f32.tf32.tf32.f32 "
        "{%0,%1,%2,%3}, {%4,%5,%6,%7}, {%8,%9}, {%0,%1,%2,%3};"
        : "+f"(c[0]), "+f"(c[1]), "+f"(c[2]), "+f"(c[3])
        : "r"(a[0]), "r"(a[1]), "r"(a[2]), "r"(a[3]), "r"(b[0]), "r"(b[1]));
}

__device__ __forceinline__ void mma_block(
    const uint32_t (*As)[136], const uint32_t (*Bs)[136],
    float acc[2][8][4], int warp_m, int warp_n, int quad, int tq)
{
    #pragma unroll
    for (int ks = 0; ks < 2; ks++) {
        int kb = ks * 8;
        uint32_t af[2][4];
        #pragma unroll
        for (int mt = 0; mt < 2; mt++) {
            int m = warp_m * 32 + mt * 16 + quad;
            af[mt][0] = As[kb + tq][m];
            af[mt][1] = As[kb + tq][m + 8];
            af[mt][2] = As[kb + tq + 4][m];
            af[mt][3] = As[kb + tq + 4][m + 8];
        }
        #pragma unroll
        for (int nt = 0; nt < 8; nt++) {
            uint32_t bf[2];
            int n = warp_n * 64 + nt * 8 + quad;
            bf[0] = Bs[kb + tq][n];
            bf[1] = Bs[kb + tq + 4][n];
            #pragma unroll
            for (int mt = 0; mt < 2; mt++) mma8(acc[mt][nt], af[mt], bf);
        }
    }
}

// ---------------- small kernels ---------------------------------------------
__global__ void k_consts(const float* __restrict__ decay,
                         const float* __restrict__ log_alpha) {
    float g = 1.f / (1.f + expf(-decay[0]));
    g_consts[0] = logf(g);
    g_consts[1] = expf(log_alpha[0]);
}

__global__ void k_zeroW() {
    size_t i = (size_t)blockIdx.x * blockDim.x + threadIdx.x;
    if (i < (size_t)B_ * D_ * D_) g_W[0][i] = 0.f;
}

// xn = x * rsqrt(mean(x^2)+eps) * norm_w
__global__ void k_xnorm(const float* __restrict__ x, const float* __restrict__ nw) {
    int warp = threadIdx.x >> 5, lane = threadIdx.x & 31;
    int row = blockIdx.x * 8 + warp;
    const float* p = x + (size_t)row * D_;
    float s = 0.f;
    #pragma unroll
    for (int i = lane; i < D_; i += 32) { float v = p[i]; s += v * v; }
    #pragma unroll
    for (int o = 16; o; o >>= 1) s += __shfl_xor_sync(0xffffffffu, s, o);
    float inv = rsqrtf(s * (1.f / D_) + 1e-5f);
    float* q = g_xn + (size_t)row * D_;
    #pragma unroll
    for (int i = lane; i < D_; i += 32) q[i] = p[i] * inv * nw[i];
}

// 8 timesteps per thread: causal depthwise conv(4) + silu, times silu'd gate
__global__ void k_conv(const float* __restrict__ cw, const float* __restrict__ cb) {
    int e = blockIdx.x * 256 + threadIdx.x;
    int t0 = blockIdx.y * 8;
    int b = blockIdx.z;
    size_t base = ((size_t)b * T_ + t0) * DI_ + e;
    float w0 = cw[e*4+0], w1 = cw[e*4+1], w2 = cw[e*4+2], w3 = cw[e*4+3];
    float bias = cb[e];
    float h0 = (t0 >= 3) ? g_val[base - 3*(size_t)DI_] : 0.f;
    float h1 = (t0 >= 2) ? g_val[base - 2*(size_t)DI_] : 0.f;
    float h2 = (t0 >= 1) ? g_val[base - 1*(size_t)DI_] : 0.f;
    #pragma unroll
    for (int j = 0; j < 8; j++) {
        size_t idx = base + (size_t)j * DI_;
        float cur = g_val[idx];
        float v = bias + w0*h0 + w1*h1 + w2*h2 + w3*cur;
        h0 = h1; h1 = h2; h2 = cur;
        float s = v / (1.f + __expf(-v));
        g_gate[idx] = s * g_gate[idx];
    }
}

// ---------------- fp16 TN GEMM: C[m,n] = f(sum_k A[m,k]*B[n,k]) -------------
// mode 0: acc ; 1: silu(acc) ; 2: add1+add2+alpha*acc
__global__ __launch_bounds__(256, 2) void k_hgemm(
    const float* __restrict__ A, const float* __restrict__ Bm,
    float* __restrict__ C, int N, int K,
    int mode, const float* __restrict__ add1, const float* __restrict__ add2)
{
    __shared__ __half As[128*SH_];
    __shared__ __half Bs[128*SH_];
    int tid = threadIdx.x;
    int m0 = blockIdx.y * 128, n0 = blockIdx.x * 128;
    int warp = tid >> 5, lane = tid & 31;
    int warp_m = warp >> 1, warp_n = warp & 1;
    int g = lane >> 2, tq = lane & 3;
    int row2 = tid >> 1, cb2 = (tid & 1) << 4;
    float acc[2][8][4] = {};

    const float* Arow = A + (size_t)(m0 + row2) * K + cb2;
    const float* Brow = Bm + (size_t)(n0 + row2) * K + cb2;
    __half* Asw = As + row2 * SH_ + cb2;
    __half* Bsw = Bs + row2 * SH_ + cb2;

    for (int k0 = 0; k0 < K; k0 += 32) {
        #pragma unroll
        for (int j = 0; j < 4; j++) {
            st4h(Asw + j*4, *(const float4*)(Arow + k0 + j*4));
            st4h(Bsw + j*4, *(const float4*)(Brow + k0 + j*4));
        }
        __syncthreads();
        mma_block_h(As, Bs, acc, warp_m, warp_n, g, tq);
        __syncthreads();
    }

    float alpha = (mode == 2) ? g_consts[1] : 0.f;
    #pragma unroll
    for (int mt = 0; mt < 2; mt++)
        #pragma unroll
        for (int h = 0; h < 2; h++) {
            int mi = m0 + warp_m * 32 + mt * 16 + g + h * 8;
            size_t row = (size_t)mi * N;
            #pragma unroll
            for (int nt = 0; nt < 8; nt++) {
                int ni = n0 + warp_n * 64 + nt * 8 + tq * 2;
                float c0 = acc[mt][nt][h*2 + 0];
                float c1 = acc[mt][nt][h*2 + 1];
                if (mode == 1) {
                    c0 = c0 / (1.f + __expf(-c0));
                    c1 = c1 / (1.f + __expf(-c1));
                } else if (mode == 2) {
                    float2 a1 = *(const float2*)(add1 + row + ni);
                    float2 a2 = *(const float2*)(add2 + row + ni);
                    c0 = a1.x + a2.x + alpha * c0;
                    c1 = a1.y + a2.y + alpha * c1;
                }
                *(float2*)(C + row + ni) = make_float2(c0, c1);
            }
        }
}

// ---------------- batched pchunk (fp16 core) --------------------------------
// P[s,b][i][j] = (i>j) ? (r_i . k_j) * gamma^(i-1-j) : 0 ;  k_j = out[t0+j-1]
__global__ __launch_bounds__(256, 2) void k_pchunk() {
    int zb = blockIdx.z; int s = zb >> 3; int b = zb & 7;
    int t0 = s * CB_;
    __shared__ __half As[128*SH_];
    __shared__ __half Bs[128*SH_];
    __shared__ float gpow[256];
    int tid = threadIdx.x;
    int m0 = blockIdx.y * 128, n0 = blockIdx.x * 128;
    int warp = tid >> 5, lane = tid & 31;
    int warp_m = warp >> 1, warp_n = warp & 1;
    int g = lane >> 2, tq = lane & 3;
    int row2 = tid >> 1, cb2 = (tid & 1) << 4;
    float acc[2][8][4] = {};
    gpow[tid] = __expf((float)tid * g_consts[0]);

    const float* Arow = g_out + ((size_t)b * T_ + t0 + m0 + row2) * D_ + cb2;
    int tok = t0 + n0 + row2 - 1;
    const float* Brow = g_out + ((size_t)b * T_ + tok) * D_ + cb2;
    bool bzero = (tok < 0);
    __half* Asw = As + row2 * SH_ + cb2;
    __half* Bsw = Bs + row2 * SH_ + cb2;
    float4 z4 = make_float4(0.f, 0.f, 0.f, 0.f);

    for (int k0 = 0; k0 < D_; k0 += 32) {
        #pragma unroll
        for (int j = 0; j < 4; j++) {
            st4h(Asw + j*4, *(const float4*)(Arow + k0 + j*4));
            st4h(Bsw + j*4, bzero ? z4 : *(const float4*)(Brow + k0 + j*4));
        }
        __syncthreads();
        mma_block_h(As, Bs, acc, warp_m, warp_n, g, tq);
        __syncthreads();
    }

    float* P = g_P + ((size_t)(s * B_ + b)) * CB_ * CB_;
    #pragma unroll
    for (int mt = 0; mt < 2; mt++)
        #pragma unroll
        for (int h = 0; h < 2; h++) {
            int ii = m0 + warp_m * 32 + mt * 16 + g + h * 8;
            #pragma unroll
            for (int nt = 0; nt < 8; nt++) {
                int jj = n0 + warp_n * 64 + nt * 8 + tq * 2;
                float c0 = (ii > jj)     ? acc[mt][nt][h*2+0] * gpow[ii-1-jj] : 0.f;
                float c1 = (ii > jj + 1) ? acc[mt][nt][h*2+1] * gpow[ii-2-jj] : 0.f;
                *(float2*)(P + (size_t)ii * CB_ + jj) = make_float2(c0, c1);
            }
        }
}

// ---------------- batched intra: g_reads = P @ v (tf32 k-major core) --------
__global__ __launch_bounds__(256, 2) void k_intra() {
    int zb = blockIdx.z; int s = zb >> 3; int b = zb & 7;
    int t0 = s * CB_;
    const float* P = g_P + ((size_t)(s * B_ + b)) * CB_ * CB_;
    __shared__ uint32_t As[16][136];
    __shared__ uint32_t Bs[16][136];
    int tid = threadIdx.x;
    int m0 = blockIdx.y * 128, n0 = blockIdx.x * 128;
    int warp = tid >> 5, lane = tid & 31;
    int warp_m = warp >> 1, warp_n = warp & 1;
    int quad = lane >> 2, tq = lane & 3;
    int r = tid >> 2, kc = (tid & 3) << 2;
    int ki2 = tid >> 4, cc = (tid & 15) << 3;
    float acc[2][8][4] = {};

    for (int k0 = 0; k0 < CB_; k0 += 16) {
        #pragma unroll
        for (int it = 0; it < 2; it++) {
            int rr = r + it * 64;
            float4 av = *(const float4*)(P + (size_t)(m0 + rr) * CB_ + k0 + kc);
            As[kc+0][rr] = f2tf(av.x); As[kc+1][rr] = f2tf(av.y);
            As[kc+2][rr] = f2tf(av.z); As[kc+3][rr] = f2tf(av.w);
        }
        const float* brow = g_v + ((size_t)b*T_ + t0 + k0 + ki2) * D_ + n0 + cc;
        float4 b0 = *(const float4*)(brow);
        float4 b1 = *(const float4*)(brow + 4);
        Bs[ki2][cc+0] = f2tf(b0.x); Bs[ki2][cc+1] = f2tf(b0.y);
        Bs[ki2][cc+2] = f2tf(b0.z); Bs[ki2][cc+3] = f2tf(b0.w);
        Bs[ki2][cc+4] = f2tf(b1.x); Bs[ki2][cc+5] = f2tf(b1.y);
        Bs[ki2][cc+6] = f2tf(b1.z); Bs[ki2][cc+7] = f2tf(b1.w);
        __syncthreads();
        mma_block(As, Bs, acc, warp_m, warp_n, quad, tq);
        __syncthreads();
    }

    #pragma unroll
    for (int mt = 0; mt < 2; mt++)
        #pragma unroll
        for (int h = 0; h < 2; h++) {
            int mi = m0 + warp_m * 32 + mt * 16 + quad + h * 8;
            size_t row = ((size_t)b * T_ + t0 + mi) * D_;
            #pragma unroll
            for (int nt = 0; nt < 8; nt++) {
                int ni = n0 + warp_n * 64 + nt * 8 + tq * 2;
                *(float2*)(g_reads + row + ni) =
                    make_float2(acc[mt][nt][h*2+0], acc[mt][nt][h*2+1]);
            }
        }
}

// ---------------- merged sequential step (tf32 cores) -----------------------
// y<6:  Wn[d,e] = gamma^CB * Wc[d,e] + sum_i gw(i) v[i,d] k[i,e]
// y>=6: g_reads[i,d] += gamma^i * sum_e r[i,e] Wc[d,e]
__global__ __launch_bounds__(256, 2) void k_step(int t0,
        const float* __restrict__ Wc, float* __restrict__ Wn) {
    int b = blockIdx.z;
    __shared__ uint32_t As[16][136];
    __shared__ uint32_t Bs[16][136];
    int tid = threadIdx.x;
    int warp = tid >> 5, lane = tid & 31;
    int warp_m = warp >> 1, warp_n = warp & 1;
    int quad = lane >> 2, tq = lane & 3;
    int r = tid >> 2, kc = (tid & 3) << 2;
    int ki2 = tid >> 4, cc = (tid & 15) << 3;
    float lg = g_consts[0];
    float acc[2][8][4] = {};
    int n0 = blockIdx.x * 128;

    if (blockIdx.y < 6) {
        int m0 = blockIdx.y * 128;
        for (int k0 = 0; k0 < CB_; k0 += 16) {
            int i = k0 + ki2;
            float gw = __expf((float)(CB_ - 1 - i) * lg);
            const float* arow = g_v + ((size_t)b*T_ + t0 + i) * D_ + m0 + cc;
            float4 a0 = *(const float4*)(arow);
            float4 a1 = *(const float4*)(arow + 4);
            As[ki2][cc+0] = f2tf(a0.x*gw); As[ki2][cc+1] = f2tf(a0.y*gw);
            As[ki2][cc+2] = f2tf(a0.z*gw); As[ki2][cc+3] = f2tf(a0.w*gw);
            As[ki2][cc+4] = f2tf(a1.x*gw); As[ki2][cc+5] = f2tf(a1.y*gw);
            As[ki2][cc+6] = f2tf(a1.z*gw); As[ki2][cc+7] = f2tf(a1.w*gw);
            int tok = t0 + i - 1;
            float4 b0 = make_float4(0.f,0.f,0.f,0.f), b1 = b0;
            if (tok >= 0) {
                const float* brow = g_out + ((size_t)b*T_ + tok) * D_ + n0 + cc;
                b0 = *(const float4*)(brow);
                b1 = *(const float4*)(brow + 4);
            }
            Bs[ki2][cc+0] = f2tf(b0.x); Bs[ki2][cc+1] = f2tf(b0.y);
            Bs[ki2][cc+2] = f2tf(b0.z); Bs[ki2][cc+3] = f2tf(b0.w);
            Bs[ki2][cc+4] = f2tf(b1.x); Bs[ki2][cc+5] = f2tf(b1.y);
            Bs[ki2][cc+6] = f2tf(b1.z); Bs[ki2][cc+7] = f2tf(b1.w);
            __syncthreads();
            mma_block(As, Bs, acc, warp_m, warp_n, quad, tq);
            __syncthreads();
        }
        float gC = __expf((float)CB_ * lg);
        size_t base = (size_t)b * D_ * D_;
        #pragma unroll
        for (int mt = 0; mt < 2; mt++)
            #pragma unroll
            for (int h = 0; h < 2; h++) {
                int d = m0 + warp_m * 32 + mt * 16 + quad + h * 8;
                #pragma unroll
                for (int nt = 0; nt < 8; nt++) {
                    int e = n0 + warp_n * 64 + nt * 8 + tq * 2;
                    size_t idx = base + (size_t)d * D_ + e;
                    float2 w = *(const float2*)(Wc + idx);
                    *(float2*)(Wn + idx) = make_float2(gC*w.x + acc[mt][nt][h*2+0],
                                                       gC*w.y + acc[mt][nt][h*2+1]);
                }
            }
    } else {
        int m0 = (blockIdx.y - 6) * 128;
        const float* A  = g_out + ((size_t)b * T_ + t0) * D_;
        const float* Wb = Wc + (size_t)b * D_ * D_;
        for (int k0 = 0; k0 < D_; k0 += 16) {
            #pragma unroll
            for (int it = 0; it < 2; it++) {
                int rr = r + it * 64;
                float4 av = *(const float4*)(A  + (size_t)(m0 + rr) * D_ + k0 + kc);
                As[kc+0][rr] = f2tf(av.x); As[kc+1][rr] = f2tf(av.y);
                As[kc+2][rr] = f2tf(av.z); As[kc+3][rr] = f2tf(av.w);
                float4 bv = *(const float4*)(Wb + (size_t)(n0 + rr) * D_ + k0 + kc);
                Bs[kc+0][rr] = f2tf(bv.x); Bs[kc+1][rr] = f2tf(bv.y);
                Bs[kc+2][rr] = f2tf(bv.z); Bs[kc+3][rr] = f2tf(bv.w);
            }
            __syncthreads();
            mma_block(As, Bs, acc, warp_m, warp_n, quad, tq);
            __syncthreads();
        }
        #pragma unroll
        for (int mt = 0; mt < 2; mt++)
            #pragma unroll
            for (int h = 0; h < 2; h++) {
                int mi = m0 + warp_m * 32 + mt * 16 + quad + h * 8;
                float sc = __expf((float)mi * lg);
                size_t row = ((size_t)b * T_ + t0 + mi) * D_;
                #pragma unroll
                for (int nt = 0; nt < 8; nt++) {
                    int ni = n0 + warp_n * 64 + nt * 8 + tq * 2;
                    float2 old = *(const float2*)(g_reads + row + ni);
                    *(float2*)(g_reads + row + ni) =
                        make_float2(old.x + sc * acc[mt][nt][h*2+0],
                                    old.y + sc * acc[mt][nt][h*2+1]);
                }
            }
    }
}

// ---------------- launch ----------------------------------------------------
extern "C" void kernel_launch(void* const* d_in, const int* in_sizes, int n_in,
                              void* d_out, int out_size) {
    const float* x         = (const float*)d_in[0];
    const float* norm_w    = (const float*)d_in[1];
    const float* proj_w    = (const float*)d_in[2];
    const float* gate_w    = (const float*)d_in[3];
    const float* conv_w    = (const float*)d_in[4];
    const float* conv_b    = (const float*)d_in[5];
    const float* out_proj  = (const float*)d_in[6];
    const float* write_w   = (const float*)d_in[7];
    const float* read_w    = (const float*)d_in[8];
    const float* decay     = (const float*)d_in[9];
    const float* log_alpha = (const float*)d_in[10];
    float* out = (float*)d_out;

    float *p_xn, *p_val, *p_gate, *p_out, *p_v, *p_reads, *p_W;
    cudaGetSymbolAddress((void**)&p_xn,    g_xn);
    cudaGetSymbolAddress((void**)&p_val,   g_val);
    cudaGetSymbolAddress((void**)&p_gate,  g_gate);
    cudaGetSymbolAddress((void**)&p_out,   g_out);
    cudaGetSymbolAddress((void**)&p_v,     g_v);
    cudaGetSymbolAddress((void**)&p_reads, g_reads);
    cudaGetSymbolAddress((void**)&p_W,     g_W);
    float* p_W0 = p_W;
    float* p_W1 = p_W + (size_t)B_ * D_ * D_;

    k_consts<<<1, 1>>>(decay, log_alpha);
    k_xnorm<<<M_/8, 256>>>(x, norm_w);

    // val = xn @ proj^T ; gate = silu(xn @ gate^T)
    k_hgemm<<<dim3(DI_/128, M_/128), 256>>>(p_xn, proj_w, p_val, DI_, D_,
                                            0, nullptr, nullptr);
    k_hgemm<<<dim3(DI_/128, M_/128), 256>>>(p_xn, gate_w, p_gate, DI_, D_,
                                            1, nullptr, nullptr);
    // h = silu(conv(val)+b) * gate  (into g_gate)
    k_conv<<<dim3(DI_/256, T_/8, B_), 256>>>(conv_w, conv_b);
    // out = h @ out_proj^T
    k_hgemm<<<dim3(D_/128, M_/128), 256>>>(p_gate, out_proj, p_out, D_, DI_,
                                           0, nullptr, nullptr);
    // v = out @ write^T
    k_hgemm<<<dim3(D_/128, M_/128), 256>>>(p_out, write_w, p_v, D_, D_,
                                           0, nullptr, nullptr);

    // batched chunk-local work (independent of W)
    k_pchunk<<<dim3(CB_/128, CB_/128, NSTEP_*B_), 256>>>();
    k_intra <<<dim3(D_/128,  CB_/128, NSTEP_*B_), 256>>>();

    // sequential state chain: wupdate + inter-reads merged per step
    k_zeroW<<<(int)(((size_t)B_*D_*D_ + 1023) / 1024), 1024>>>();
    const float* Wc = p_W0;
    float* Wn = p_W1;
    for (int s = 0; s < NSTEP_; s++) {
        k_step<<<dim3(D_/128, 8, B_), 256>>>(s * CB_, Wc, Wn);
        float* tmp = (float*)Wc; Wc = Wn; Wn = tmp;
    }

    // final: y = x + out + alpha * (reads @ read^T)
    k_hgemm<<<dim3(D_/128, M_/128), 256>>>(p_reads, read_w, out, D_, D_,
                                           2, x, p_out);
}

// round 7
// speedup vs baseline: 2.2533x; 1.3116x over previous
#include <cuda_runtime.h>
#include <cuda_fp16.h>
#include <math.h>
#include <stdint.h>

#define B_ 8
#define T_ 4096
#define D_ 768
#define DI_ 1536
#define M_ (B_*T_)          // 32768 rows
#define CB_ 256             // big chunk
#define NSTEP_ (T_/CB_)     // 16
#define SH_ 40              // fp16 SMEM row stride (halfs) for scan kernels
#define SROW_ 40            // fp16 SMEM row stride (halfs) for pipelined GEMM
#define NKST_ 3             // cp.async stages
#define STAGE_HALFS_ (128*SROW_)

// ---------------- scratch ---------------------------------------------------
__device__ float g_val[(size_t)M_*DI_];
__device__ float g_gate[(size_t)M_*DI_];
__device__ float g_out[(size_t)M_*D_];
__device__ float g_v[(size_t)M_*D_];
__device__ float g_reads[(size_t)M_*D_];
__device__ float g_W[2][(size_t)B_*D_*D_];
__device__ float g_P[(size_t)B_*NSTEP_*CB_*CB_];
__device__ __half g_xnh[(size_t)M_*D_];
__device__ __half g_hh[(size_t)M_*DI_];
__device__ __half g_outh[(size_t)M_*D_];
__device__ __half g_readsh[(size_t)M_*D_];
__device__ __half g_wh[4718592];             // fp16 weight copies
__device__ float g_consts[2];                // [0]=log(gamma), [1]=alpha

// ---------------- helpers ---------------------------------------------------
__device__ __forceinline__ uint32_t f2tf(float f) {
    uint32_t u;
    asm("cvt.rna.tf32.f32 %0, %1;" : "=r"(u) : "f"(f));
    return u;
}

__device__ __forceinline__ void st4h(__half* dst, float4 v) {
    __half2 lo = __floats2half2_rn(v.x, v.y);
    __half2 hi = __floats2half2_rn(v.z, v.w);
    uint2 u;
    u.x = *(uint32_t*)&lo;
    u.y = *(uint32_t*)&hi;
    *(uint2*)dst = u;
}

#define CP_ASYNC16(dst, src) \
    asm volatile("cp.async.ca.shared.global [%0], [%1], 16;" :: "r"(dst), "l"(src))
#define CP_COMMIT()  asm volatile("cp.async.commit_group;" ::: "memory")
#define CP_WAIT1()   asm volatile("cp.async.wait_group 1;" ::: "memory")

#define LDSM4(r, addr) \
    asm volatile("ldmatrix.sync.aligned.m8n8.x4.shared.b16 {%0,%1,%2,%3}, [%4];" \
        : "=r"((r)[0]), "=r"((r)[1]), "=r"((r)[2]), "=r"((r)[3]) : "r"(addr))

__device__ __forceinline__ void mma_h(float* c, const uint32_t* a, const uint32_t* b) {
    asm volatile(
        "mma.sync.aligned.m16n8k16.row.col.f32.f16.f16.f32 "
        "{%0,%1,%2,%3}, {%4,%5,%6,%7}, {%8,%9}, {%0,%1,%2,%3};"
        : "+f"(c[0]), "+f"(c[1]), "+f"(c[2]), "+f"(c[3])
        : "r"(a[0]), "r"(a[1]), "r"(a[2]), "r"(a[3]), "r"(b[0]), "r"(b[1]));
}

// ---- legacy fp16 core for pchunk (SMEM [128][SH_], scalar frag loads) ------
__device__ __forceinline__ void mma_block_h(
    const __half* As, const __half* Bs, float acc[2][8][4],
    int warp_m, int warp_n, int g, int tq)
{
    #pragma unroll
    for (int ks = 0; ks < 32; ks += 16) {
        uint32_t af[2][4];
        #pragma unroll
        for (int mt = 0; mt < 2; mt++) {
            const __half* p = As + (warp_m*32 + mt*16 + g)*SH_ + ks + tq*2;
            af[mt][0] = *(const uint32_t*)p;
            af[mt][1] = *(const uint32_t*)(p + 8*SH_);
            af[mt][2] = *(const uint32_t*)(p + 8);
            af[mt][3] = *(const uint32_t*)(p + 8*SH_ + 8);
        }
        #pragma unroll
        for (int nt = 0; nt < 8; nt++) {
            const __half* q = Bs + (warp_n*64 + nt*8 + g)*SH_ + ks + tq*2;
            uint32_t bf[2];
            bf[0] = *(const uint32_t*)q;
            bf[1] = *(const uint32_t*)(q + 8);
            mma_h(acc[0][nt], af[0], bf);
            mma_h(acc[1][nt], af[1], bf);
        }
    }
}

// ---- tf32 k-major core for transpose contractions --------------------------
__device__ __forceinline__ void mma8(float* c, const uint32_t* a, const uint32_t* b) {
    asm volatile(
        "mma.sync.aligned.m16n8k8.row.col.f32.tf32.tf32.f32 "
        "{%0,%1,%2,%3}, {%4,%5,%6,%7}, {%8,%9}, {%0,%1,%2,%3};"
        : "+f"(c[0]), "+f"(c[1]), "+f"(c[2]), "+f"(c[3])
        : "r"(a[0]), "r"(a[1]), "r"(a[2]), "r"(a[3]), "r"(b[0]), "r"(b[1]));
}

__device__ __forceinline__ void mma_block(
    const uint32_t (*As)[136], const uint32_t (*Bs)[136],
    float acc[2][8][4], int warp_m, int warp_n, int quad, int tq)
{
    #pragma unroll
    for (int ks = 0; ks < 2; ks++) {
        int kb = ks * 8;
        uint32_t af[2][4];
        #pragma unroll
        for (int mt = 0; mt < 2; mt++) {
            int m = warp_m * 32 + mt * 16 + quad;
            af[mt][0] = As[kb + tq][m];
            af[mt][1] = As[kb + tq][m + 8];
            af[mt][2] = As[kb + tq + 4][m];
            af[mt][3] = As[kb + tq + 4][m + 8];
        }
        #pragma unroll
        for (int nt = 0; nt < 8; nt++) {
            uint32_t bf[2];
            int n = warp_n * 64 + nt * 8 + quad;
            bf[0] = Bs[kb + tq][n];
            bf[1] = Bs[kb + tq + 4][n];
            #pragma unroll
            for (int mt = 0; mt < 2; mt++) mma8(acc[mt][nt], af[mt], bf);
        }
    }
}

// ---------------- small kernels ---------------------------------------------
__global__ void k_consts(const float* __restrict__ decay,
                         const float* __restrict__ log_alpha) {
    float g = 1.f / (1.f + expf(-decay[0]));
    g_consts[0] = logf(g);
    g_consts[1] = expf(log_alpha[0]);
}

__global__ void k_zeroW() {
    size_t i = (size_t)blockIdx.x * blockDim.x + threadIdx.x;
    if (i < (size_t)B_ * D_ * D_) g_W[0][i] = 0.f;
}

// fp32 -> fp16 convert (pairs)
__global__ void k_h2(const float* __restrict__ src, __half* __restrict__ dst, int n2) {
    int i = blockIdx.x * 256 + threadIdx.x;
    if (i < n2) {
        float2 v = *(const float2*)(src + i * 2);
        *(__half2*)(dst + i * 2) = __floats2half2_rn(v.x, v.y);
    }
}

// xn(fp16) = x * rsqrt(mean(x^2)+eps) * norm_w
__global__ void k_xnorm(const float* __restrict__ x, const float* __restrict__ nw) {
    int warp = threadIdx.x >> 5, lane = threadIdx.x & 31;
    int row = blockIdx.x * 8 + warp;
    const float* p = x + (size_t)row * D_;
    float s = 0.f;
    #pragma unroll
    for (int i = lane; i < D_; i += 32) { float v = p[i]; s += v * v; }
    #pragma unroll
    for (int o = 16; o; o >>= 1) s += __shfl_xor_sync(0xffffffffu, s, o);
    float inv = rsqrtf(s * (1.f / D_) + 1e-5f);
    __half* q = g_xnh + (size_t)row * D_;
    #pragma unroll
    for (int i = lane; i < D_; i += 32) q[i] = __float2half(p[i] * inv * nw[i]);
}

// conv + silu + gate -> fp16 h
__global__ void k_conv(const float* __restrict__ cw, const float* __restrict__ cb) {
    int e = blockIdx.x * 256 + threadIdx.x;
    int t0 = blockIdx.y * 8;
    int b = blockIdx.z;
    size_t base = ((size_t)b * T_ + t0) * DI_ + e;
    float w0 = cw[e*4+0], w1 = cw[e*4+1], w2 = cw[e*4+2], w3 = cw[e*4+3];
    float bias = cb[e];
    float h0 = (t0 >= 3) ? g_val[base - 3*(size_t)DI_] : 0.f;
    float h1 = (t0 >= 2) ? g_val[base - 2*(size_t)DI_] : 0.f;
    float h2 = (t0 >= 1) ? g_val[base - 1*(size_t)DI_] : 0.f;
    #pragma unroll
    for (int j = 0; j < 8; j++) {
        size_t idx = base + (size_t)j * DI_;
        float cur = g_val[idx];
        float v = bias + w0*h0 + w1*h1 + w2*h2 + w3*cur;
        h0 = h1; h1 = h2; h2 = cur;
        float s = v / (1.f + __expf(-v));
        g_hh[idx] = __float2half(s * g_gate[idx]);
    }
}

// ---------------- pipelined fp16 TN GEMM ------------------------------------
// A[M,K], B[N,K] fp16 k-contiguous. C fp32, optional Ch fp16 dual-store.
// mode 0: acc ; 1: silu(acc) ; 2: add1+add2+alpha*acc
__global__ __launch_bounds__(256, 2) void k_hgemm16(
    const __half* __restrict__ A, const __half* __restrict__ Bm,
    float* __restrict__ C, __half* __restrict__ Ch, int N, int K,
    int mode, const float* __restrict__ add1, const float* __restrict__ add2)
{
    extern __shared__ __align__(16) __half sm16[];
    __half* As = sm16;
    __half* Bs = sm16 + NKST_ * STAGE_HALFS_;
    int tid = threadIdx.x;
    int m0 = blockIdx.y * 128, n0 = blockIdx.x * 128;
    int warp = tid >> 5, lane = tid & 31;
    int warp_m = warp >> 1, warp_n = warp & 1;
    int g = lane >> 2, tq = lane & 3;
    float acc[2][8][4] = {};

    // cp.async mapping: thread -> row tid/2, chunks (tid&1)*2 + {0,1}
    int lrow = tid >> 1, lc = (tid & 1) * 2;
    const __half* Ag = A + (size_t)(m0 + lrow) * K + lc * 8;
    const __half* Bg = Bm + (size_t)(n0 + lrow) * K + lc * 8;
    uint32_t aBase = (uint32_t)__cvta_generic_to_shared(As);
    uint32_t bBase = (uint32_t)__cvta_generic_to_shared(Bs);
    uint32_t dA = aBase + (lrow * SROW_ + lc * 8) * 2;
    uint32_t dB = bBase + (lrow * SROW_ + lc * 8) * 2;

    int nk = K >> 5;
    auto ISSUE = [&](int s) {
        uint32_t offs = (uint32_t)(s % NKST_) * (STAGE_HALFS_ * 2);
        const __half* ag = Ag + s * 32;
        const __half* bg = Bg + s * 32;
        CP_ASYNC16(dA + offs, ag);
        CP_ASYNC16(dA + offs + 16, ag + 8);
        CP_ASYNC16(dB + offs, bg);
        CP_ASYNC16(dB + offs + 16, bg + 8);
    };

    ISSUE(0); CP_COMMIT();
    if (nk > 1) ISSUE(1);
    CP_COMMIT();

    int lr = lane & 15, lk = (lane >> 4) << 3;
    for (int s = 0; s < nk; s++) {
        CP_WAIT1();
        __syncthreads();
        if (s + 2 < nk) ISSUE(s + 2);
        CP_COMMIT();

        uint32_t st = (uint32_t)(s % NKST_) * (STAGE_HALFS_ * 2);
        uint32_t aS = aBase + st, bS = bBase + st;
        #pragma unroll
        for (int ks = 0; ks < 32; ks += 16) {
            uint32_t a0 = aS + ((warp_m * 32 + lr) * SROW_ + ks + lk) * 2;
            uint32_t af0[4], af1[4];
            LDSM4(af0, a0);
            LDSM4(af1, a0 + 16 * SROW_ * 2);
            #pragma unroll
            for (int p = 0; p < 4; p++) {
                uint32_t bb = bS + ((warp_n * 64 + p * 16 + lr) * SROW_ + ks + lk) * 2;
                uint32_t bf[4];
                LDSM4(bf, bb);
                uint32_t be[2] = { bf[0], bf[2] };
                uint32_t bo[2] = { bf[1], bf[3] };
                mma_h(acc[0][2*p],   af0, be);
                mma_h(acc[1][2*p],   af1, be);
                mma_h(acc[0][2*p+1], af0, bo);
                mma_h(acc[1][2*p+1], af1, bo);
            }
        }
        __syncthreads();
    }

    float alpha = (mode == 2) ? g_consts[1] : 0.f;
    #pragma unroll
    for (int mt = 0; mt < 2; mt++)
        #pragma unroll
        for (int h = 0; h < 2; h++) {
            int mi = m0 + warp_m * 32 + mt * 16 + g + h * 8;
            size_t row = (size_t)mi * N;
            #pragma unroll
            for (int nt = 0; nt < 8; nt++) {
                int ni = n0 + warp_n * 64 + nt * 8 + tq * 2;
                float c0 = acc[mt][nt][h*2 + 0];
                float c1 = acc[mt][nt][h*2 + 1];
                if (mode == 1) {
                    c0 = c0 / (1.f + __expf(-c0));
                    c1 = c1 / (1.f + __expf(-c1));
                } else if (mode == 2) {
                    float2 a1 = *(const float2*)(add1 + row + ni);
                    float2 a2 = *(const float2*)(add2 + row + ni);
                    c0 = a1.x + a2.x + alpha * c0;
                    c1 = a1.y + a2.y + alpha * c1;
                }
                *(float2*)(C + row + ni) = make_float2(c0, c1);
                if (Ch) *(__half2*)(Ch + row + ni) = __floats2half2_rn(c0, c1);
            }
        }
}

// ---------------- batched pchunk (fp16 core, unchanged) ---------------------
__global__ __launch_bounds__(256, 2) void k_pchunk() {
    int zb = blockIdx.z; int s = zb >> 3; int b = zb & 7;
    int t0 = s * CB_;
    __shared__ __half As[128*SH_];
    __shared__ __half Bs[128*SH_];
    __shared__ float gpow[256];
    int tid = threadIdx.x;
    int m0 = blockIdx.y * 128, n0 = blockIdx.x * 128;
    int warp = tid >> 5, lane = tid & 31;
    int warp_m = warp >> 1, warp_n = warp & 1;
    int g = lane >> 2, tq = lane & 3;
    int row2 = tid >> 1, cb2 = (tid & 1) << 4;
    float acc[2][8][4] = {};
    gpow[tid] = __expf((float)tid * g_consts[0]);

    const float* Arow = g_out + ((size_t)b * T_ + t0 + m0 + row2) * D_ + cb2;
    int tok = t0 + n0 + row2 - 1;
    const float* Brow = g_out + ((size_t)b * T_ + tok) * D_ + cb2;
    bool bzero = (tok < 0);
    __half* Asw = As + row2 * SH_ + cb2;
    __half* Bsw = Bs + row2 * SH_ + cb2;
    float4 z4 = make_float4(0.f, 0.f, 0.f, 0.f);

    for (int k0 = 0; k0 < D_; k0 += 32) {
        #pragma unroll
        for (int j = 0; j < 4; j++) {
            st4h(Asw + j*4, *(const float4*)(Arow + k0 + j*4));
            st4h(Bsw + j*4, bzero ? z4 : *(const float4*)(Brow + k0 + j*4));
        }
        __syncthreads();
        mma_block_h(As, Bs, acc, warp_m, warp_n, g, tq);
        __syncthreads();
    }

    float* P = g_P + ((size_t)(s * B_ + b)) * CB_ * CB_;
    #pragma unroll
    for (int mt = 0; mt < 2; mt++)
        #pragma unroll
        for (int h = 0; h < 2; h++) {
            int ii = m0 + warp_m * 32 + mt * 16 + g + h * 8;
            #pragma unroll
            for (int nt = 0; nt < 8; nt++) {
                int jj = n0 + warp_n * 64 + nt * 8 + tq * 2;
                float c0 = (ii > jj)     ? acc[mt][nt][h*2+0] * gpow[ii-1-jj] : 0.f;
                float c1 = (ii > jj + 1) ? acc[mt][nt][h*2+1] * gpow[ii-2-jj] : 0.f;
                *(float2*)(P + (size_t)ii * CB_ + jj) = make_float2(c0, c1);
            }
        }
}

// ---------------- batched intra: g_reads = P @ v (tf32 core) ----------------
__global__ __launch_bounds__(256, 2) void k_intra() {
    int zb = blockIdx.z; int s = zb >> 3; int b = zb & 7;
    int t0 = s * CB_;
    const float* P = g_P + ((size_t)(s * B_ + b)) * CB_ * CB_;
    __shared__ uint32_t As[16][136];
    __shared__ uint32_t Bs[16][136];
    int tid = threadIdx.x;
    int m0 = blockIdx.y * 128, n0 = blockIdx.x * 128;
    int warp = tid >> 5, lane = tid & 31;
    int warp_m = warp >> 1, warp_n = warp & 1;
    int quad = lane >> 2, tq = lane & 3;
    int r = tid >> 2, kc = (tid & 3) << 2;
    int ki2 = tid >> 4, cc = (tid & 15) << 3;
    float acc[2][8][4] = {};

    for (int k0 = 0; k0 < CB_; k0 += 16) {
        #pragma unroll
        for (int it = 0; it < 2; it++) {
            int rr = r + it * 64;
            float4 av = *(const float4*)(P + (size_t)(m0 + rr) * CB_ + k0 + kc);
            As[kc+0][rr] = f2tf(av.x); As[kc+1][rr] = f2tf(av.y);
            As[kc+2][rr] = f2tf(av.z); As[kc+3][rr] = f2tf(av.w);
        }
        const float* brow = g_v + ((size_t)b*T_ + t0 + k0 + ki2) * D_ + n0 + cc;
        float4 b0 = *(const float4*)(brow);
        float4 b1 = *(const float4*)(brow + 4);
        Bs[ki2][cc+0] = f2tf(b0.x); Bs[ki2][cc+1] = f2tf(b0.y);
        Bs[ki2][cc+2] = f2tf(b0.z); Bs[ki2][cc+3] = f2tf(b0.w);
        Bs[ki2][cc+4] = f2tf(b1.x); Bs[ki2][cc+5] = f2tf(b1.y);
        Bs[ki2][cc+6] = f2tf(b1.z); Bs[ki2][cc+7] = f2tf(b1.w);
        __syncthreads();
        mma_block(As, Bs, acc, warp_m, warp_n, quad, tq);
        __syncthreads();
    }

    #pragma unroll
    for (int mt = 0; mt < 2; mt++)
        #pragma unroll
        for (int h = 0; h < 2; h++) {
            int mi = m0 + warp_m * 32 + mt * 16 + quad + h * 8;
            size_t row = ((size_t)b * T_ + t0 + mi) * D_;
            #pragma unroll
            for (int nt = 0; nt < 8; nt++) {
                int ni = n0 + warp_n * 64 + nt * 8 + tq * 2;
                *(float2*)(g_reads + row + ni) =
                    make_float2(acc[mt][nt][h*2+0], acc[mt][nt][h*2+1]);
            }
        }
}

// ---------------- merged sequential step (tf32 cores) -----------------------
__global__ __launch_bounds__(256, 2) void k_step(int t0,
        const float* __restrict__ Wc, float* __restrict__ Wn) {
    int b = blockIdx.z;
    __shared__ uint32_t As[16][136];
    __shared__ uint32_t Bs[16][136];
    int tid = threadIdx.x;
    int warp = tid >> 5, lane = tid & 31;
    int warp_m = warp >> 1, warp_n = warp & 1;
    int quad = lane >> 2, tq = lane & 3;
    int r = tid >> 2, kc = (tid & 3) << 2;
    int ki2 = tid >> 4, cc = (tid & 15) << 3;
    float lg = g_consts[0];
    float acc[2][8][4] = {};
    int n0 = blockIdx.x * 128;

    if (blockIdx.y < 6) {
        int m0 = blockIdx.y * 128;
        for (int k0 = 0; k0 < CB_; k0 += 16) {
            int i = k0 + ki2;
            float gw = __expf((float)(CB_ - 1 - i) * lg);
            const float* arow = g_v + ((size_t)b*T_ + t0 + i) * D_ + m0 + cc;
            float4 a0 = *(const float4*)(arow);
            float4 a1 = *(const float4*)(arow + 4);
            As[ki2][cc+0] = f2tf(a0.x*gw); As[ki2][cc+1] = f2tf(a0.y*gw);
            As[ki2][cc+2] = f2tf(a0.z*gw); As[ki2][cc+3] = f2tf(a0.w*gw);
            As[ki2][cc+4] = f2tf(a1.x*gw); As[ki2][cc+5] = f2tf(a1.y*gw);
            As[ki2][cc+6] = f2tf(a1.z*gw); As[ki2][cc+7] = f2tf(a1.w*gw);
            int tok = t0 + i - 1;
            float4 b0 = make_float4(0.f,0.f,0.f,0.f), b1 = b0;
            if (tok >= 0) {
                const float* brow = g_out + ((size_t)b*T_ + tok) * D_ + n0 + cc;
                b0 = *(const float4*)(brow);
                b1 = *(const float4*)(brow + 4);
            }
            Bs[ki2][cc+0] = f2tf(b0.x); Bs[ki2][cc+1] = f2tf(b0.y);
            Bs[ki2][cc+2] = f2tf(b0.z); Bs[ki2][cc+3] = f2tf(b0.w);
            Bs[ki2][cc+4] = f2tf(b1.x); Bs[ki2][cc+5] = f2tf(b1.y);
            Bs[ki2][cc+6] = f2tf(b1.z); Bs[ki2][cc+7] = f2tf(b1.w);
            __syncthreads();
            mma_block(As, Bs, acc, warp_m, warp_n, quad, tq);
            __syncthreads();
        }
        float gC = __expf((float)CB_ * lg);
        size_t base = (size_t)b * D_ * D_;
        #pragma unroll
        for (int mt = 0; mt < 2; mt++)
            #pragma unroll
            for (int h = 0; h < 2; h++) {
                int d = m0 + warp_m * 32 + mt * 16 + quad + h * 8;
                #pragma unroll
                for (int nt = 0; nt < 8; nt++) {
                    int e = n0 + warp_n * 64 + nt * 8 + tq * 2;
                    size_t idx = base + (size_t)d * D_ + e;
                    float2 w = *(const float2*)(Wc + idx);
                    *(float2*)(Wn + idx) = make_float2(gC*w.x + acc[mt][nt][h*2+0],
                                                       gC*w.y + acc[mt][nt][h*2+1]);
                }
            }
    } else {
        int m0 = (blockIdx.y - 6) * 128;
        const float* A  = g_out + ((size_t)b * T_ + t0) * D_;
        const float* Wb = Wc + (size_t)b * D_ * D_;
        for (int k0 = 0; k0 < D_; k0 += 16) {
            #pragma unroll
            for (int it = 0; it < 2; it++) {
                int rr = r + it * 64;
                float4 av = *(const float4*)(A  + (size_t)(m0 + rr) * D_ + k0 + kc);
                As[kc+0][rr] = f2tf(av.x); As[kc+1][rr] = f2tf(av.y);
                As[kc+2][rr] = f2tf(av.z); As[kc+3][rr] = f2tf(av.w);
                float4 bv = *(const float4*)(Wb + (size_t)(n0 + rr) * D_ + k0 + kc);
                Bs[kc+0][rr] = f2tf(bv.x); Bs[kc+1][rr] = f2tf(bv.y);
                Bs[kc+2][rr] = f2tf(bv.z); Bs[kc+3][rr] = f2tf(bv.w);
            }
            __syncthreads();
            mma_block(As, Bs, acc, warp_m, warp_n, quad, tq);
            __syncthreads();
        }
        #pragma unroll
        for (int mt = 0; mt < 2; mt++)
            #pragma unroll
            for (int h = 0; h < 2; h++) {
                int mi = m0 + warp_m * 32 + mt * 16 + quad + h * 8;
                float sc = __expf((float)mi * lg);
                size_t row = ((size_t)b * T_ + t0 + mi) * D_;
                #pragma unroll
                for (int nt = 0; nt < 8; nt++) {
                    int ni = n0 + warp_n * 64 + nt * 8 + tq * 2;
                    float2 old = *(const float2*)(g_reads + row + ni);
                    *(float2*)(g_reads + row + ni) =
                        make_float2(old.x + sc * acc[mt][nt][h*2+0],
                                    old.y + sc * acc[mt][nt][h*2+1]);
                }
            }
    }
}

// ---------------- launch ----------------------------------------------------
extern "C" void kernel_launch(void* const* d_in, const int* in_sizes, int n_in,
                              void* d_out, int out_size) {
    const float* x         = (const float*)d_in[0];
    const float* norm_w    = (const float*)d_in[1];
    const float* proj_w    = (const float*)d_in[2];
    const float* gate_w    = (const float*)d_in[3];
    const float* conv_w    = (const float*)d_in[4];
    const float* conv_b    = (const float*)d_in[5];
    const float* out_proj  = (const float*)d_in[6];
    const float* write_w   = (const float*)d_in[7];
    const float* read_w    = (const float*)d_in[8];
    const float* decay     = (const float*)d_in[9];
    const float* log_alpha = (const float*)d_in[10];
    float* out = (float*)d_out;

    float *p_val, *p_gate, *p_out, *p_v, *p_reads, *p_W;
    __half *p_xnh, *p_hh, *p_outh, *p_readsh, *p_wh;
    cudaGetSymbolAddress((void**)&p_val,    g_val);
    cudaGetSymbolAddress((void**)&p_gate,   g_gate);
    cudaGetSymbolAddress((void**)&p_out,    g_out);
    cudaGetSymbolAddress((void**)&p_v,      g_v);
    cudaGetSymbolAddress((void**)&p_reads,  g_reads);
    cudaGetSymbolAddress((void**)&p_W,      g_W);
    cudaGetSymbolAddress((void**)&p_xnh,    g_xnh);
    cudaGetSymbolAddress((void**)&p_hh,     g_hh);
    cudaGetSymbolAddress((void**)&p_outh,   g_outh);
    cudaGetSymbolAddress((void**)&p_readsh, g_readsh);
    cudaGetSymbolAddress((void**)&p_wh,     g_wh);
    float* p_W0 = p_W;
    float* p_W1 = p_W + (size_t)B_ * D_ * D_;
    __half* wh_proj  = p_wh;
    __half* wh_gate  = p_wh + 1179648;
    __half* wh_outp  = p_wh + 2359296;
    __half* wh_write = p_wh + 3538944;
    __half* wh_read  = p_wh + 4128768;

    static int smem_set = 0;
    if (!smem_set) {
        cudaFuncSetAttribute(k_hgemm16, cudaFuncAttributeMaxDynamicSharedMemorySize,
                             2 * NKST_ * STAGE_HALFS_ * 2);
        smem_set = 1;
    }
    const int GSM = 2 * NKST_ * STAGE_HALFS_ * 2;   // 61440 B

    k_consts<<<1, 1>>>(decay, log_alpha);
    k_h2<<<(DI_*D_/2+255)/256, 256>>>(proj_w,   wh_proj,  DI_*D_/2);
    k_h2<<<(DI_*D_/2+255)/256, 256>>>(gate_w,   wh_gate,  DI_*D_/2);
    k_h2<<<(DI_*D_/2+255)/256, 256>>>(out_proj, wh_outp,  D_*DI_/2);
    k_h2<<<(D_*D_/2+255)/256,  256>>>(write_w,  wh_write, D_*D_/2);
    k_h2<<<(D_*D_/2+255)/256,  256>>>(read_w,   wh_read,  D_*D_/2);
    k_xnorm<<<M_/8, 256>>>(x, norm_w);

    // val = xn @ proj^T ; gate = silu(xn @ gate^T)
    k_hgemm16<<<dim3(DI_/128, M_/128), 256, GSM>>>(
        p_xnh, wh_proj, p_val, nullptr, DI_, D_, 0, nullptr, nullptr);
    k_hgemm16<<<dim3(DI_/128, M_/128), 256, GSM>>>(
        p_xnh, wh_gate, p_gate, nullptr, DI_, D_, 1, nullptr, nullptr);
    // h(fp16) = silu(conv(val)+b) * gate
    k_conv<<<dim3(DI_/256, T_/8, B_), 256>>>(conv_w, conv_b);
    // out = h @ out_proj^T  (dual-store fp32 + fp16)
    k_hgemm16<<<dim3(D_/128, M_/128), 256, GSM>>>(
        p_hh, wh_outp, p_out, p_outh, D_, DI_, 0, nullptr, nullptr);
    // v = out @ write^T
    k_hgemm16<<<dim3(D_/128, M_/128), 256, GSM>>>(
        p_outh, wh_write, p_v, nullptr, D_, D_, 0, nullptr, nullptr);

    // batched chunk-local work
    k_pchunk<<<dim3(CB_/128, CB_/128, NSTEP_*B_), 256>>>();
    k_intra <<<dim3(D_/128,  CB_/128, NSTEP_*B_), 256>>>();

    // sequential state chain
    k_zeroW<<<(int)(((size_t)B_*D_*D_ + 1023) / 1024), 1024>>>();
    const float* Wc = p_W0;
    float* Wn = p_W1;
    for (int s = 0; s < NSTEP_; s++) {
        k_step<<<dim3(D_/128, 8, B_), 256>>>(s * CB_, Wc, Wn);
        float* tmp = (float*)Wc; Wc = Wn; Wn = tmp;
    }

    // final: y = x + out + alpha * (reads @ read^T)
    k_h2<<<((int)((size_t)M_*D_/2)+255)/256, 256>>>(p_reads, p_readsh, (int)((size_t)M_*D_/2));
    k_hgemm16<<<dim3(D_/128, M_/128), 256, GSM>>>(
        p_readsh, wh_read, out, nullptr, D_, D_, 2, x, p_out);
}

// round 8
// speedup vs baseline: 3.1433x; 1.3950x over previous
#include <cuda_runtime.h>
#include <cuda_fp16.h>
#include <math.h>
#include <stdint.h>

#define B_ 8
#define T_ 4096
#define D_ 768
#define DI_ 1536
#define M_ (B_*T_)          // 32768 rows
#define CB_ 256             // chunk
#define NSTEP_ (T_/CB_)     // 16
#define SROW_ 40            // fp16 SMEM row stride (halfs)
#define NKST_ 3             // cp.async stages
#define STAGE_HALFS_ (128*SROW_)
#define GSM_ (2*NKST_*STAGE_HALFS_*2)   // 61440 bytes dynamic SMEM

// ---------------- scratch ---------------------------------------------------
__device__ float g_val[(size_t)M_*DI_];
__device__ float g_gate[(size_t)M_*DI_];
__device__ float g_out[(size_t)M_*D_];
__device__ float g_v[(size_t)M_*D_];
__device__ float g_reads[(size_t)M_*D_];
__device__ float g_W[2][(size_t)B_*D_*D_];
__device__ __half g_Wh[2][(size_t)B_*D_*D_];
__device__ __half g_Ph[(size_t)B_*NSTEP_*CB_*CB_];
__device__ __half g_xnh[(size_t)M_*D_];
__device__ __half g_hh[(size_t)M_*DI_];
__device__ __half g_outh[(size_t)M_*D_];
__device__ __half g_vh[(size_t)M_*D_];
__device__ __half g_vT[(size_t)M_*D_];     // [b][d][t]
__device__ __half g_vTs[(size_t)M_*D_];    // [b][d][t] * gamma^(CB-1-(t%CB))
__device__ __half g_koutT[(size_t)M_*D_];  // [b][e][t] = out[t-1][e]
__device__ __half g_readsh[(size_t)M_*D_];
__device__ __half g_wh[4718592];           // fp16 weight copies
__device__ float g_consts[2];              // [0]=log(gamma), [1]=alpha

// ---------------- asm helpers ------------------------------------------------
#define CP_ASYNC16(dst, src) \
    asm volatile("cp.async.ca.shared.global [%0], [%1], 16;" :: "r"(dst), "l"(src))
#define CP_ASYNC16Z(dst, src, sz) \
    asm volatile("cp.async.ca.shared.global [%0], [%1], 16, %2;" :: "r"(dst), "l"(src), "r"(sz))
#define CP_COMMIT()  asm volatile("cp.async.commit_group;" ::: "memory")
#define CP_WAIT1()   asm volatile("cp.async.wait_group 1;" ::: "memory")

#define LDSM4(r, addr) \
    asm volatile("ldmatrix.sync.aligned.m8n8.x4.shared.b16 {%0,%1,%2,%3}, [%4];" \
        : "=r"((r)[0]), "=r"((r)[1]), "=r"((r)[2]), "=r"((r)[3]) : "r"(addr))

__device__ __forceinline__ void mma_h(float* c, const uint32_t* a, const uint32_t* b) {
    asm volatile(
        "mma.sync.aligned.m16n8k16.row.col.f32.f16.f16.f32 "
        "{%0,%1,%2,%3}, {%4,%5,%6,%7}, {%8,%9}, {%0,%1,%2,%3};"
        : "+f"(c[0]), "+f"(c[1]), "+f"(c[2]), "+f"(c[3])
        : "r"(a[0]), "r"(a[1]), "r"(a[2]), "r"(a[3]), "r"(b[0]), "r"(b[1]));
}

// ---------------- shared pipelined fp16 mainloop -----------------------------
// Ag/Bg pre-offset per-thread to (row0+lrow)*ld + lc*8; k advances 32/stage.
// bsz: 16 normally, 0 to zero-fill this thread's B row.
__device__ __forceinline__ void hloop(
    const __half* __restrict__ Ag, const __half* __restrict__ Bg,
    int nk, int bsz, __half* As, __half* Bs, float acc[2][8][4],
    int warp_m, int warp_n, int lane, int tid)
{
    int lrow = tid >> 1, lc = (tid & 1) * 2;
    uint32_t aBase = (uint32_t)__cvta_generic_to_shared(As);
    uint32_t bBase = (uint32_t)__cvta_generic_to_shared(Bs);
    uint32_t dA = aBase + (lrow * SROW_ + lc * 8) * 2;
    uint32_t dB = bBase + (lrow * SROW_ + lc * 8) * 2;

    auto ISSUE = [&](int s) {
        uint32_t offs = (uint32_t)(s % NKST_) * (STAGE_HALFS_ * 2);
        const __half* ag = Ag + s * 32;
        const __half* bg = Bg + s * 32;
        CP_ASYNC16(dA + offs, ag);
        CP_ASYNC16(dA + offs + 16, ag + 8);
        CP_ASYNC16Z(dB + offs, bg, bsz);
        CP_ASYNC16Z(dB + offs + 16, bg + 8, bsz);
    };

    ISSUE(0); CP_COMMIT();
    if (nk > 1) ISSUE(1);
    CP_COMMIT();

    int lr = lane & 15, lk = (lane >> 4) << 3;
    for (int s = 0; s < nk; s++) {
        CP_WAIT1();
        __syncthreads();
        if (s + 2 < nk) ISSUE(s + 2);
        CP_COMMIT();

        uint32_t st = (uint32_t)(s % NKST_) * (STAGE_HALFS_ * 2);
        uint32_t aS = aBase + st, bS = bBase + st;
        #pragma unroll
        for (int ks = 0; ks < 32; ks += 16) {
            uint32_t a0 = aS + ((warp_m * 32 + lr) * SROW_ + ks + lk) * 2;
            uint32_t af0[4], af1[4];
            LDSM4(af0, a0);
            LDSM4(af1, a0 + 16 * SROW_ * 2);
            #pragma unroll
            for (int p = 0; p < 4; p++) {
                uint32_t bb = bS + ((warp_n * 64 + p * 16 + lr) * SROW_ + ks + lk) * 2;
                uint32_t bf[4];
                LDSM4(bf, bb);
                uint32_t be[2] = { bf[0], bf[2] };
                uint32_t bo[2] = { bf[1], bf[3] };
                mma_h(acc[0][2*p],   af0, be);
                mma_h(acc[1][2*p],   af1, be);
                mma_h(acc[0][2*p+1], af0, bo);
                mma_h(acc[1][2*p+1], af1, bo);
            }
        }
        __syncthreads();
    }
}

// ---------------- small kernels ---------------------------------------------
__global__ void k_consts(const float* __restrict__ decay,
                         const float* __restrict__ log_alpha) {
    float g = 1.f / (1.f + expf(-decay[0]));
    g_consts[0] = logf(g);
    g_consts[1] = expf(log_alpha[0]);
}

__global__ void k_zeroW() {
    size_t i = (size_t)blockIdx.x * blockDim.x + threadIdx.x;
    if (i < (size_t)B_ * D_ * D_) {
        g_W[0][i] = 0.f;
        g_Wh[0][i] = __float2half(0.f);
    }
}

__global__ void k_h2(const float* __restrict__ src, __half* __restrict__ dst, int n2) {
    int i = blockIdx.x * 256 + threadIdx.x;
    if (i < n2) {
        float2 v = *(const float2*)(src + i * 2);
        *(__half2*)(dst + i * 2) = __floats2half2_rn(v.x, v.y);
    }
}

__global__ void k_xnorm(const float* __restrict__ x, const float* __restrict__ nw) {
    int warp = threadIdx.x >> 5, lane = threadIdx.x & 31;
    int row = blockIdx.x * 8 + warp;
    const float* p = x + (size_t)row * D_;
    float s = 0.f;
    #pragma unroll
    for (int i = lane; i < D_; i += 32) { float v = p[i]; s += v * v; }
    #pragma unroll
    for (int o = 16; o; o >>= 1) s += __shfl_xor_sync(0xffffffffu, s, o);
    float inv = rsqrtf(s * (1.f / D_) + 1e-5f);
    __half* q = g_xnh + (size_t)row * D_;
    #pragma unroll
    for (int i = lane; i < D_; i += 32) q[i] = __float2half(p[i] * inv * nw[i]);
}

__global__ void k_conv(const float* __restrict__ cw, const float* __restrict__ cb) {
    int e = blockIdx.x * 256 + threadIdx.x;
    int t0 = blockIdx.y * 8;
    int b = blockIdx.z;
    size_t base = ((size_t)b * T_ + t0) * DI_ + e;
    float w0 = cw[e*4+0], w1 = cw[e*4+1], w2 = cw[e*4+2], w3 = cw[e*4+3];
    float bias = cb[e];
    float h0 = (t0 >= 3) ? g_val[base - 3*(size_t)DI_] : 0.f;
    float h1 = (t0 >= 2) ? g_val[base - 2*(size_t)DI_] : 0.f;
    float h2 = (t0 >= 1) ? g_val[base - 1*(size_t)DI_] : 0.f;
    #pragma unroll
    for (int j = 0; j < 8; j++) {
        size_t idx = base + (size_t)j * DI_;
        float cur = g_val[idx];
        float v = bias + w0*h0 + w1*h1 + w2*h2 + w3*cur;
        h0 = h1; h1 = h2; h2 = cur;
        float s = v / (1.f + __expf(-v));
        g_hh[idx] = __float2half(s * g_gate[idx]);
    }
}

// 32x32 tile transposes -------------------------------------------------------
// vT[d][t] = vh[t][d] ; vTs = vT * gamma^(CB-1-(t%CB))
__global__ void k_transV() {
    __shared__ __half sm[32][33];
    int b = blockIdx.z;
    int t0 = blockIdx.x * 32, d0 = blockIdx.y * 32;
    int tx = threadIdx.x & 31, ty = threadIdx.x >> 5;
    #pragma unroll
    for (int j = 0; j < 4; j++)
        sm[ty + j*8][tx] = g_vh[((size_t)b*T_ + t0 + ty + j*8)*D_ + d0 + tx];
    __syncthreads();
    float gw = __expf((float)(CB_ - 1 - ((t0 + tx) % CB_)) * g_consts[0]);
    #pragma unroll
    for (int j = 0; j < 4; j++) {
        size_t o = ((size_t)b*D_ + d0 + ty + j*8)*T_ + t0 + tx;
        __half v = sm[tx][ty + j*8];
        g_vT[o] = v;
        g_vTs[o] = __float2half(__half2float(v) * gw);
    }
}

// koutT[e][t] = outh[t-1][e] (0 at t=0)
__global__ void k_transK() {
    __shared__ __half sm[32][33];
    int b = blockIdx.z;
    int t0 = blockIdx.x * 32, d0 = blockIdx.y * 32;
    int tx = threadIdx.x & 31, ty = threadIdx.x >> 5;
    #pragma unroll
    for (int j = 0; j < 4; j++) {
        int t = t0 + ty + j*8;
        sm[ty + j*8][tx] = (t > 0)
            ? g_outh[((size_t)b*T_ + t - 1)*D_ + d0 + tx] : __float2half(0.f);
    }
    __syncthreads();
    #pragma unroll
    for (int j = 0; j < 4; j++)
        g_koutT[((size_t)b*D_ + d0 + ty + j*8)*T_ + t0 + tx] = sm[tx][ty + j*8];
}

// ---------------- dense fp16 TN GEMM -----------------------------------------
// mode 0: acc ; 1: silu ; 2: add1+add2+alpha*acc. Optional fp16 dual-store.
__global__ __launch_bounds__(256, 2) void k_hgemm16(
    const __half* __restrict__ A, const __half* __restrict__ Bm,
    float* __restrict__ C, __half* __restrict__ Ch, int N, int K,
    int mode, const float* __restrict__ add1, const float* __restrict__ add2)
{
    extern __shared__ __align__(16) __half sm16[];
    __half* As = sm16;
    __half* Bs = sm16 + NKST_ * STAGE_HALFS_;
    int tid = threadIdx.x;
    int m0 = blockIdx.y * 128, n0 = blockIdx.x * 128;
    int warp = tid >> 5, lane = tid & 31;
    int warp_m = warp >> 1, warp_n = warp & 1;
    int g = lane >> 2, tq = lane & 3;
    int lrow = tid >> 1, lc = (tid & 1) * 2;
    float acc[2][8][4] = {};

    hloop(A + (size_t)(m0 + lrow) * K + lc * 8,
          Bm + (size_t)(n0 + lrow) * K + lc * 8,
          K >> 5, 16, As, Bs, acc, warp_m, warp_n, lane, tid);

    float alpha = (mode == 2) ? g_consts[1] : 0.f;
    #pragma unroll
    for (int mt = 0; mt < 2; mt++)
        #pragma unroll
        for (int h = 0; h < 2; h++) {
            int mi = m0 + warp_m * 32 + mt * 16 + g + h * 8;
            size_t row = (size_t)mi * N;
            #pragma unroll
            for (int nt = 0; nt < 8; nt++) {
                int ni = n0 + warp_n * 64 + nt * 8 + tq * 2;
                float c0 = acc[mt][nt][h*2 + 0];
                float c1 = acc[mt][nt][h*2 + 1];
                if (mode == 1) {
                    c0 = c0 / (1.f + __expf(-c0));
                    c1 = c1 / (1.f + __expf(-c1));
                } else if (mode == 2) {
                    float2 a1 = *(const float2*)(add1 + row + ni);
                    float2 a2 = *(const float2*)(add2 + row + ni);
                    c0 = a1.x + a2.x + alpha * c0;
                    c1 = a1.y + a2.y + alpha * c1;
                }
                *(float2*)(C + row + ni) = make_float2(c0, c1);
                if (Ch) *(__half2*)(Ch + row + ni) = __floats2half2_rn(c0, c1);
            }
        }
}

// ---------------- batched pchunk: P = mask(r@k^T) -> fp16 -------------------
__global__ __launch_bounds__(256, 2) void k_pchunk() {
    extern __shared__ __align__(16) __half sm16[];
    __half* As = sm16;
    __half* Bs = sm16 + NKST_ * STAGE_HALFS_;
    __shared__ float gpow[256];
    int zb = blockIdx.z; int s = zb >> 3; int b = zb & 7;
    int t0 = s * CB_;
    int tid = threadIdx.x;
    int m0 = blockIdx.y * 128, n0 = blockIdx.x * 128;
    int warp = tid >> 5, lane = tid & 31;
    int warp_m = warp >> 1, warp_n = warp & 1;
    int g = lane >> 2, tq = lane & 3;
    int lrow = tid >> 1, lc = (tid & 1) * 2;
    float acc[2][8][4] = {};
    gpow[tid] = __expf((float)tid * g_consts[0]);

    int tok = t0 + n0 + lrow - 1;
    int bsz = (tok >= 0) ? 16 : 0;
    int tokc = (tok >= 0) ? tok : 0;
    hloop(g_outh + ((size_t)b*T_ + t0 + m0 + lrow)*D_ + lc*8,
          g_outh + ((size_t)b*T_ + tokc)*D_ + lc*8,
          D_ >> 5, bsz, As, Bs, acc, warp_m, warp_n, lane, tid);

    __half* P = g_Ph + (size_t)(s * B_ + b) * CB_ * CB_;
    #pragma unroll
    for (int mt = 0; mt < 2; mt++)
        #pragma unroll
        for (int h = 0; h < 2; h++) {
            int ii = m0 + warp_m * 32 + mt * 16 + g + h * 8;
            #pragma unroll
            for (int nt = 0; nt < 8; nt++) {
                int jj = n0 + warp_n * 64 + nt * 8 + tq * 2;
                float c0 = (ii > jj)     ? acc[mt][nt][h*2+0] * gpow[ii-1-jj] : 0.f;
                float c1 = (ii > jj + 1) ? acc[mt][nt][h*2+1] * gpow[ii-2-jj] : 0.f;
                *(__half2*)(P + (size_t)ii * CB_ + jj) = __floats2half2_rn(c0, c1);
            }
        }
}

// ---------------- batched intra: g_reads = P @ v ----------------------------
__global__ __launch_bounds__(256, 2) void k_intra() {
    extern __shared__ __align__(16) __half sm16[];
    __half* As = sm16;
    __half* Bs = sm16 + NKST_ * STAGE_HALFS_;
    int zb = blockIdx.z; int s = zb >> 3; int b = zb & 7;
    int t0 = s * CB_;
    int tid = threadIdx.x;
    int m0 = blockIdx.y * 128, n0 = blockIdx.x * 128;   // m over CB, n over D
    int warp = tid >> 5, lane = tid & 31;
    int warp_m = warp >> 1, warp_n = warp & 1;
    int g = lane >> 2, tq = lane & 3;
    int lrow = tid >> 1, lc = (tid & 1) * 2;
    float acc[2][8][4] = {};

    hloop(g_Ph + (size_t)(s * B_ + b) * CB_ * CB_ + (size_t)(m0 + lrow) * CB_ + lc*8,
          g_vT + ((size_t)b*D_ + n0 + lrow)*T_ + t0 + lc*8,
          CB_ >> 5, 16, As, Bs, acc, warp_m, warp_n, lane, tid);

    #pragma unroll
    for (int mt = 0; mt < 2; mt++)
        #pragma unroll
        for (int h = 0; h < 2; h++) {
            int mi = m0 + warp_m * 32 + mt * 16 + g + h * 8;
            size_t row = ((size_t)b * T_ + t0 + mi) * D_;
            #pragma unroll
            for (int nt = 0; nt < 8; nt++) {
                int ni = n0 + warp_n * 64 + nt * 8 + tq * 2;
                *(float2*)(g_reads + row + ni) =
                    make_float2(acc[mt][nt][h*2+0], acc[mt][nt][h*2+1]);
            }
        }
}

// ---------------- merged sequential step (all fp16 pipelined) ---------------
// y<6:  Wn = gamma^CB * Wc + vTs @ koutT^T   (contract over i)
// y>=6: g_reads += gamma^i * out @ Wc^T      (contract over e)
__global__ __launch_bounds__(256, 2) void k_step(int t0,
        const float* __restrict__ Wc32, float* __restrict__ Wn32,
        const __half* __restrict__ Whc, __half* __restrict__ Whn) {
    extern __shared__ __align__(16) __half sm16[];
    __half* As = sm16;
    __half* Bs = sm16 + NKST_ * STAGE_HALFS_;
    int b = blockIdx.z;
    int tid = threadIdx.x;
    int warp = tid >> 5, lane = tid & 31;
    int warp_m = warp >> 1, warp_n = warp & 1;
    int g = lane >> 2, tq = lane & 3;
    int lrow = tid >> 1, lc = (tid & 1) * 2;
    float lg = g_consts[0];
    float acc[2][8][4] = {};
    int n0 = blockIdx.x * 128;

    if (blockIdx.y < 6) {
        int m0 = blockIdx.y * 128;
        hloop(g_vTs + ((size_t)b*D_ + m0 + lrow)*T_ + t0 + lc*8,
              g_koutT + ((size_t)b*D_ + n0 + lrow)*T_ + t0 + lc*8,
              CB_ >> 5, 16, As, Bs, acc, warp_m, warp_n, lane, tid);

        float gC = __expf((float)CB_ * lg);
        size_t base = (size_t)b * D_ * D_;
        #pragma unroll
        for (int mt = 0; mt < 2; mt++)
            #pragma unroll
            for (int h = 0; h < 2; h++) {
                int d = m0 + warp_m * 32 + mt * 16 + g + h * 8;
                #pragma unroll
                for (int nt = 0; nt < 8; nt++) {
                    int e = n0 + warp_n * 64 + nt * 8 + tq * 2;
                    size_t idx = base + (size_t)d * D_ + e;
                    float2 w = *(const float2*)(Wc32 + idx);
                    float n0v = gC * w.x + acc[mt][nt][h*2+0];
                    float n1v = gC * w.y + acc[mt][nt][h*2+1];
                    *(float2*)(Wn32 + idx) = make_float2(n0v, n1v);
                    *(__half2*)(Whn + idx) = __floats2half2_rn(n0v, n1v);
                }
            }
    } else {
        int m0 = (blockIdx.y - 6) * 128;
        hloop(g_outh + ((size_t)b*T_ + t0 + m0 + lrow)*D_ + lc*8,
              Whc + ((size_t)b*D_ + n0 + lrow)*D_ + lc*8,
              D_ >> 5, 16, As, Bs, acc, warp_m, warp_n, lane, tid);

        #pragma unroll
        for (int mt = 0; mt < 2; mt++)
            #pragma unroll
            for (int h = 0; h < 2; h++) {
                int mi = m0 + warp_m * 32 + mt * 16 + g + h * 8;
                float sc = __expf((float)mi * lg);
                size_t row = ((size_t)b * T_ + t0 + mi) * D_;
                #pragma unroll
                for (int nt = 0; nt < 8; nt++) {
                    int ni = n0 + warp_n * 64 + nt * 8 + tq * 2;
                    float2 old = *(const float2*)(g_reads + row + ni);
                    *(float2*)(g_reads + row + ni) =
                        make_float2(old.x + sc * acc[mt][nt][h*2+0],
                                    old.y + sc * acc[mt][nt][h*2+1]);
                }
            }
    }
}

// ---------------- launch ----------------------------------------------------
extern "C" void kernel_launch(void* const* d_in, const int* in_sizes, int n_in,
                              void* d_out, int out_size) {
    const float* x         = (const float*)d_in[0];
    const float* norm_w    = (const float*)d_in[1];
    const float* proj_w    = (const float*)d_in[2];
    const float* gate_w    = (const float*)d_in[3];
    const float* conv_w    = (const float*)d_in[4];
    const float* conv_b    = (const float*)d_in[5];
    const float* out_proj  = (const float*)d_in[6];
    const float* write_w   = (const float*)d_in[7];
    const float* read_w    = (const float*)d_in[8];
    const float* decay     = (const float*)d_in[9];
    const float* log_alpha = (const float*)d_in[10];
    float* out = (float*)d_out;

    float *p_val, *p_gate, *p_out, *p_v, *p_reads, *p_W;
    __half *p_xnh, *p_hh, *p_outh, *p_vh, *p_readsh, *p_wh, *p_Wh;
    cudaGetSymbolAddress((void**)&p_val,    g_val);
    cudaGetSymbolAddress((void**)&p_gate,   g_gate);
    cudaGetSymbolAddress((void**)&p_out,    g_out);
    cudaGetSymbolAddress((void**)&p_v,      g_v);
    cudaGetSymbolAddress((void**)&p_reads,  g_reads);
    cudaGetSymbolAddress((void**)&p_W,      g_W);
    cudaGetSymbolAddress((void**)&p_Wh,     g_Wh);
    cudaGetSymbolAddress((void**)&p_xnh,    g_xnh);
    cudaGetSymbolAddress((void**)&p_hh,     g_hh);
    cudaGetSymbolAddress((void**)&p_outh,   g_outh);
    cudaGetSymbolAddress((void**)&p_vh,     g_vh);
    cudaGetSymbolAddress((void**)&p_readsh, g_readsh);
    cudaGetSymbolAddress((void**)&p_wh,     g_wh);
    float* p_W0 = p_W;
    float* p_W1 = p_W + (size_t)B_ * D_ * D_;
    __half* p_Wh0 = p_Wh;
    __half* p_Wh1 = p_Wh + (size_t)B_ * D_ * D_;
    __half* wh_proj  = p_wh;
    __half* wh_gate  = p_wh + 1179648;
    __half* wh_outp  = p_wh + 2359296;
    __half* wh_write = p_wh + 3538944;
    __half* wh_read  = p_wh + 4128768;

    static int smem_set = 0;
    if (!smem_set) {
        cudaFuncSetAttribute(k_hgemm16, cudaFuncAttributeMaxDynamicSharedMemorySize, GSM_);
        cudaFuncSetAttribute(k_pchunk,  cudaFuncAttributeMaxDynamicSharedMemorySize, GSM_);
        cudaFuncSetAttribute(k_intra,   cudaFuncAttributeMaxDynamicSharedMemorySize, GSM_);
        cudaFuncSetAttribute(k_step,    cudaFuncAttributeMaxDynamicSharedMemorySize, GSM_);
        smem_set = 1;
    }

    k_consts<<<1, 1>>>(decay, log_alpha);
    k_h2<<<(DI_*D_/2+255)/256, 256>>>(proj_w,   wh_proj,  DI_*D_/2);
    k_h2<<<(DI_*D_/2+255)/256, 256>>>(gate_w,   wh_gate,  DI_*D_/2);
    k_h2<<<(DI_*D_/2+255)/256, 256>>>(out_proj, wh_outp,  D_*DI_/2);
    k_h2<<<(D_*D_/2+255)/256,  256>>>(write_w,  wh_write, D_*D_/2);
    k_h2<<<(D_*D_/2+255)/256,  256>>>(read_w,   wh_read,  D_*D_/2);
    k_xnorm<<<M_/8, 256>>>(x, norm_w);

    // val = xn @ proj^T ; gate = silu(xn @ gate^T)
    k_hgemm16<<<dim3(DI_/128, M_/128), 256, GSM_>>>(
        p_xnh, wh_proj, p_val, nullptr, DI_, D_, 0, nullptr, nullptr);
    k_hgemm16<<<dim3(DI_/128, M_/128), 256, GSM_>>>(
        p_xnh, wh_gate, p_gate, nullptr, DI_, D_, 1, nullptr, nullptr);
    // h(fp16) = silu(conv(val)+b) * gate
    k_conv<<<dim3(DI_/256, T_/8, B_), 256>>>(conv_w, conv_b);
    // out = h @ out_proj^T  (fp32 + fp16)
    k_hgemm16<<<dim3(D_/128, M_/128), 256, GSM_>>>(
        p_hh, wh_outp, p_out, p_outh, D_, DI_, 0, nullptr, nullptr);
    // v = out @ write^T     (fp32 + fp16)
    k_hgemm16<<<dim3(D_/128, M_/128), 256, GSM_>>>(
        p_outh, wh_write, p_v, p_vh, D_, D_, 0, nullptr, nullptr);

    // transposed fp16 operand copies
    k_transV<<<dim3(T_/32, D_/32, B_), 256>>>();
    k_transK<<<dim3(T_/32, D_/32, B_), 256>>>();

    // batched chunk-local work
    k_pchunk<<<dim3(CB_/128, CB_/128, NSTEP_*B_), 256, GSM_>>>();
    k_intra <<<dim3(D_/128,  CB_/128, NSTEP_*B_), 256, GSM_>>>();

    // sequential state chain
    k_zeroW<<<(int)(((size_t)B_*D_*D_ + 1023) / 1024), 1024>>>();
    const float* Wc = p_W0;  float* Wn = p_W1;
    const __half* Whc = p_Wh0; __half* Whn = p_Wh1;
    for (int s = 0; s < NSTEP_; s++) {
        k_step<<<dim3(D_/128, 8, B_), 256, GSM_>>>(s * CB_, Wc, Wn, Whc, Whn);
        float* t1 = (float*)Wc; Wc = Wn; Wn = t1;
        __half* t2 = (__half*)Whc; Whc = Whn; Whn = t2;
    }

    // final: y = x + out + alpha * (reads @ read^T)
    k_h2<<<((int)((size_t)M_*D_/2)+255)/256, 256>>>(p_reads, p_readsh,
                                                    (int)((size_t)M_*D_/2));
    k_hgemm16<<<dim3(D_/128, M_/128), 256, GSM_>>>(
        p_readsh, wh_read, out, nullptr, D_, D_, 2, x, p_out);
}

// round 9
// speedup vs baseline: 3.7868x; 1.2047x over previous
#include <cuda_runtime.h>
#include <cuda_fp16.h>
#include <math.h>
#include <stdint.h>

#define B_ 8
#define T_ 4096
#define D_ 768
#define DI_ 1536
#define M_ (B_*T_)          // 32768 rows
#define CB_ 256             // chunk
#define NSTEP_ (T_/CB_)     // 16
#define DD_ ((size_t)D_*D_)
#define SROW_ 40            // fp16 SMEM row stride (halfs)
#define NKST_ 3             // cp.async stages
#define STAGE_HALFS_ (128*SROW_)
#define GSM_ (2*NKST_*STAGE_HALFS_*2)   // 61440 bytes dynamic SMEM

// ---------------- scratch ---------------------------------------------------
__device__ float  g_out[(size_t)M_*D_];
__device__ __half g_xnh[(size_t)M_*D_];
__device__ __half g_valh[(size_t)M_*DI_];
__device__ __half g_gateh[(size_t)M_*DI_];
__device__ __half g_hh[(size_t)M_*DI_];
__device__ __half g_outh[(size_t)M_*D_];
__device__ __half g_vh[(size_t)M_*D_];
__device__ __half g_vT[(size_t)M_*D_];     // [b][d][t]
__device__ __half g_vTs[(size_t)M_*D_];    // [b][d][t] * gamma^(CB-1-(t%CB))
__device__ __half g_koutT[(size_t)M_*D_];  // [b][e][t] = out[t-1][e]
__device__ __half g_Ph[(size_t)B_*NSTEP_*CB_*CB_];
__device__ __half g_U[(size_t)NSTEP_*B_*D_*D_];    // per-chunk updates
__device__ __half g_Whs[(size_t)NSTEP_*B_*D_*D_];  // W prefix snapshots
__device__ __half g_readsh[(size_t)M_*D_];
__device__ __half g_wh[4718592];           // fp16 weight copies
__device__ float g_consts[2];              // [0]=log(gamma), [1]=alpha

// ---------------- asm helpers ------------------------------------------------
#define CP_ASYNC16(dst, src) \
    asm volatile("cp.async.ca.shared.global [%0], [%1], 16;" :: "r"(dst), "l"(src))
#define CP_ASYNC16Z(dst, src, sz) \
    asm volatile("cp.async.ca.shared.global [%0], [%1], 16, %2;" :: "r"(dst), "l"(src), "r"(sz))
#define CP_COMMIT()  asm volatile("cp.async.commit_group;" ::: "memory")
#define CP_WAIT1()   asm volatile("cp.async.wait_group 1;" ::: "memory")

#define LDSM4(r, addr) \
    asm volatile("ldmatrix.sync.aligned.m8n8.x4.shared.b16 {%0,%1,%2,%3}, [%4];" \
        : "=r"((r)[0]), "=r"((r)[1]), "=r"((r)[2]), "=r"((r)[3]) : "r"(addr))

__device__ __forceinline__ void mma_h(float* c, const uint32_t* a, const uint32_t* b) {
    asm volatile(
        "mma.sync.aligned.m16n8k16.row.col.f32.f16.f16.f32 "
        "{%0,%1,%2,%3}, {%4,%5,%6,%7}, {%8,%9}, {%0,%1,%2,%3};"
        : "+f"(c[0]), "+f"(c[1]), "+f"(c[2]), "+f"(c[3])
        : "r"(a[0]), "r"(a[1]), "r"(a[2]), "r"(a[3]), "r"(b[0]), "r"(b[1]));
}

// ---------------- shared pipelined fp16 mainloop -----------------------------
// Ag/Bg pre-offset per-thread to (row0+lrow)*ld + lc*8; k advances 32/stage.
// Only a leading sync per stage — iter-s reads are ordered before iter-s+1
// ISSUE by the top barrier, so no trailing sync is needed.
__device__ __forceinline__ void hloop(
    const __half* __restrict__ Ag, const __half* __restrict__ Bg,
    int nk, int bsz, __half* As, __half* Bs, float acc[2][8][4],
    int warp_m, int warp_n, int lane, int tid)
{
    int lrow = tid >> 1, lc = (tid & 1) * 2;
    uint32_t aBase = (uint32_t)__cvta_generic_to_shared(As);
    uint32_t bBase = (uint32_t)__cvta_generic_to_shared(Bs);
    uint32_t dA = aBase + (lrow * SROW_ + lc * 8) * 2;
    uint32_t dB = bBase + (lrow * SROW_ + lc * 8) * 2;

    auto ISSUE = [&](int s) {
        uint32_t offs = (uint32_t)(s % NKST_) * (STAGE_HALFS_ * 2);
        const __half* ag = Ag + s * 32;
        const __half* bg = Bg + s * 32;
        CP_ASYNC16(dA + offs, ag);
        CP_ASYNC16(dA + offs + 16, ag + 8);
        CP_ASYNC16Z(dB + offs, bg, bsz);
        CP_ASYNC16Z(dB + offs + 16, bg + 8, bsz);
    };

    ISSUE(0); CP_COMMIT();
    if (nk > 1) ISSUE(1);
    CP_COMMIT();

    int lr = lane & 15, lk = (lane >> 4) << 3;
    for (int s = 0; s < nk; s++) {
        CP_WAIT1();
        __syncthreads();
        if (s + 2 < nk) ISSUE(s + 2);
        CP_COMMIT();

        uint32_t st = (uint32_t)(s % NKST_) * (STAGE_HALFS_ * 2);
        uint32_t aS = aBase + st, bS = bBase + st;
        #pragma unroll
        for (int ks = 0; ks < 32; ks += 16) {
            uint32_t a0 = aS + ((warp_m * 32 + lr) * SROW_ + ks + lk) * 2;
            uint32_t af0[4], af1[4];
            LDSM4(af0, a0);
            LDSM4(af1, a0 + 16 * SROW_ * 2);
            #pragma unroll
            for (int p = 0; p < 4; p++) {
                uint32_t bb = bS + ((warp_n * 64 + p * 16 + lr) * SROW_ + ks + lk) * 2;
                uint32_t bf[4];
                LDSM4(bf, bb);
                uint32_t be[2] = { bf[0], bf[2] };
                uint32_t bo[2] = { bf[1], bf[3] };
                mma_h(acc[0][2*p],   af0, be);
                mma_h(acc[1][2*p],   af1, be);
                mma_h(acc[0][2*p+1], af0, bo);
                mma_h(acc[1][2*p+1], af1, bo);
            }
        }
    }
    __syncthreads();   // protect SMEM for any subsequent phase
}

// ---------------- small kernels ---------------------------------------------
__global__ void k_consts(const float* __restrict__ decay,
                         const float* __restrict__ log_alpha) {
    float g = 1.f / (1.f + expf(-decay[0]));
    g_consts[0] = logf(g);
    g_consts[1] = expf(log_alpha[0]);
}

__global__ void k_h2(const float* __restrict__ src, __half* __restrict__ dst, int n2) {
    int i = blockIdx.x * 256 + threadIdx.x;
    if (i < n2) {
        float2 v = *(const float2*)(src + i * 2);
        *(__half2*)(dst + i * 2) = __floats2half2_rn(v.x, v.y);
    }
}

__global__ void k_xnorm(const float* __restrict__ x, const float* __restrict__ nw) {
    int warp = threadIdx.x >> 5, lane = threadIdx.x & 31;
    int row = blockIdx.x * 8 + warp;
    const float* p = x + (size_t)row * D_;
    float s = 0.f;
    #pragma unroll
    for (int i = lane; i < D_; i += 32) { float v = p[i]; s += v * v; }
    #pragma unroll
    for (int o = 16; o; o >>= 1) s += __shfl_xor_sync(0xffffffffu, s, o);
    float inv = rsqrtf(s * (1.f / D_) + 1e-5f);
    __half* q = g_xnh + (size_t)row * D_;
    #pragma unroll
    for (int i = lane; i < D_; i += 32) q[i] = __float2half(p[i] * inv * nw[i]);
}

// fp16 in/out conv: h = silu(conv(val)+b) * gate
__global__ void k_conv(const float* __restrict__ cw, const float* __restrict__ cb) {
    int e = blockIdx.x * 256 + threadIdx.x;
    int t0 = blockIdx.y * 8;
    int b = blockIdx.z;
    size_t base = ((size_t)b * T_ + t0) * DI_ + e;
    float w0 = cw[e*4+0], w1 = cw[e*4+1], w2 = cw[e*4+2], w3 = cw[e*4+3];
    float bias = cb[e];
    float h0 = (t0 >= 3) ? __half2float(g_valh[base - 3*(size_t)DI_]) : 0.f;
    float h1 = (t0 >= 2) ? __half2float(g_valh[base - 2*(size_t)DI_]) : 0.f;
    float h2 = (t0 >= 1) ? __half2float(g_valh[base - 1*(size_t)DI_]) : 0.f;
    #pragma unroll
    for (int j = 0; j < 8; j++) {
        size_t idx = base + (size_t)j * DI_;
        float cur = __half2float(g_valh[idx]);
        float v = bias + w0*h0 + w1*h1 + w2*h2 + w3*cur;
        h0 = h1; h1 = h2; h2 = cur;
        float s = v / (1.f + __expf(-v));
        g_hh[idx] = __float2half(s * __half2float(g_gateh[idx]));
    }
}

// 32x32 tile transposes -------------------------------------------------------
__global__ void k_transV() {
    __shared__ __half sm[32][33];
    int b = blockIdx.z;
    int t0 = blockIdx.x * 32, d0 = blockIdx.y * 32;
    int tx = threadIdx.x & 31, ty = threadIdx.x >> 5;
    #pragma unroll
    for (int j = 0; j < 4; j++)
        sm[ty + j*8][tx] = g_vh[((size_t)b*T_ + t0 + ty + j*8)*D_ + d0 + tx];
    __syncthreads();
    float gw = __expf((float)(CB_ - 1 - ((t0 + tx) % CB_)) * g_consts[0]);
    #pragma unroll
    for (int j = 0; j < 4; j++) {
        size_t o = ((size_t)b*D_ + d0 + ty + j*8)*T_ + t0 + tx;
        __half v = sm[tx][ty + j*8];
        g_vT[o] = v;
        g_vTs[o] = __float2half(__half2float(v) * gw);
    }
}

__global__ void k_transK() {
    __shared__ __half sm[32][33];
    int b = blockIdx.z;
    int t0 = blockIdx.x * 32, d0 = blockIdx.y * 32;
    int tx = threadIdx.x & 31, ty = threadIdx.x >> 5;
    #pragma unroll
    for (int j = 0; j < 4; j++) {
        int t = t0 + ty + j*8;
        sm[ty + j*8][tx] = (t > 0)
            ? g_outh[((size_t)b*T_ + t - 1)*D_ + d0 + tx] : __float2half(0.f);
    }
    __syncthreads();
    #pragma unroll
    for (int j = 0; j < 4; j++)
        g_koutT[((size_t)b*D_ + d0 + ty + j*8)*T_ + t0 + tx] = sm[tx][ty + j*8];
}

// ---------------- dense fp16 TN GEMM -----------------------------------------
// mode 0: acc ; 1: silu ; 2: add1+add2+alpha*acc. C (fp32) / Ch (fp16) optional.
__global__ __launch_bounds__(256, 2) void k_hgemm16(
    const __half* __restrict__ A, const __half* __restrict__ Bm,
    float* __restrict__ C, __half* __restrict__ Ch, int N, int K,
    int mode, const float* __restrict__ add1, const float* __restrict__ add2)
{
    extern __shared__ __align__(16) __half sm16[];
    __half* As = sm16;
    __half* Bs = sm16 + NKST_ * STAGE_HALFS_;
    int tid = threadIdx.x;
    int m0 = blockIdx.y * 128, n0 = blockIdx.x * 128;
    int warp = tid >> 5, lane = tid & 31;
    int warp_m = warp >> 1, warp_n = warp & 1;
    int g = lane >> 2, tq = lane & 3;
    int lrow = tid >> 1, lc = (tid & 1) * 2;
    float acc[2][8][4] = {};

    hloop(A + (size_t)(m0 + lrow) * K + lc * 8,
          Bm + (size_t)(n0 + lrow) * K + lc * 8,
          K >> 5, 16, As, Bs, acc, warp_m, warp_n, lane, tid);

    float alpha = (mode == 2) ? g_consts[1] : 0.f;
    #pragma unroll
    for (int mt = 0; mt < 2; mt++)
        #pragma unroll
        for (int h = 0; h < 2; h++) {
            int mi = m0 + warp_m * 32 + mt * 16 + g + h * 8;
            size_t row = (size_t)mi * N;
            #pragma unroll
            for (int nt = 0; nt < 8; nt++) {
                int ni = n0 + warp_n * 64 + nt * 8 + tq * 2;
                float c0 = acc[mt][nt][h*2 + 0];
                float c1 = acc[mt][nt][h*2 + 1];
                if (mode == 1) {
                    c0 = c0 / (1.f + __expf(-c0));
                    c1 = c1 / (1.f + __expf(-c1));
                } else if (mode == 2) {
                    float2 a1 = *(const float2*)(add1 + row + ni);
                    float2 a2 = *(const float2*)(add2 + row + ni);
                    c0 = a1.x + a2.x + alpha * c0;
                    c1 = a1.y + a2.y + alpha * c1;
                }
                if (C)  *(float2*)(C + row + ni) = make_float2(c0, c1);
                if (Ch) *(__half2*)(Ch + row + ni) = __floats2half2_rn(c0, c1);
            }
        }
}

// ---------------- batched pchunk: P = mask(r@k^T) -> fp16 -------------------
__global__ __launch_bounds__(256, 2) void k_pchunk() {
    extern __shared__ __align__(16) __half sm16[];
    __half* As = sm16;
    __half* Bs = sm16 + NKST_ * STAGE_HALFS_;
    __shared__ float gpow[256];
    int zb = blockIdx.z; int s = zb >> 3; int b = zb & 7;
    int t0 = s * CB_;
    int tid = threadIdx.x;
    int m0 = blockIdx.y * 128, n0 = blockIdx.x * 128;
    int warp = tid >> 5, lane = tid & 31;
    int warp_m = warp >> 1, warp_n = warp & 1;
    int g = lane >> 2, tq = lane & 3;
    int lrow = tid >> 1, lc = (tid & 1) * 2;
    float acc[2][8][4] = {};
    gpow[tid] = __expf((float)tid * g_consts[0]);

    int tok = t0 + n0 + lrow - 1;
    int bsz = (tok >= 0) ? 16 : 0;
    int tokc = (tok >= 0) ? tok : 0;
    hloop(g_outh + ((size_t)b*T_ + t0 + m0 + lrow)*D_ + lc*8,
          g_outh + ((size_t)b*T_ + tokc)*D_ + lc*8,
          D_ >> 5, bsz, As, Bs, acc, warp_m, warp_n, lane, tid);

    __half* P = g_Ph + (size_t)(s * B_ + b) * CB_ * CB_;
    #pragma unroll
    for (int mt = 0; mt < 2; mt++)
        #pragma unroll
        for (int h = 0; h < 2; h++) {
            int ii = m0 + warp_m * 32 + mt * 16 + g + h * 8;
            #pragma unroll
            for (int nt = 0; nt < 8; nt++) {
                int jj = n0 + warp_n * 64 + nt * 8 + tq * 2;
                float c0 = (ii > jj)     ? acc[mt][nt][h*2+0] * gpow[ii-1-jj] : 0.f;
                float c1 = (ii > jj + 1) ? acc[mt][nt][h*2+1] * gpow[ii-2-jj] : 0.f;
                *(__half2*)(P + (size_t)ii * CB_ + jj) = __floats2half2_rn(c0, c1);
            }
        }
}

// ---------------- batched U: U_s = vTs_s @ koutT_s^T ------------------------
__global__ __launch_bounds__(256, 2) void k_updateU() {
    extern __shared__ __align__(16) __half sm16[];
    __half* As = sm16;
    __half* Bs = sm16 + NKST_ * STAGE_HALFS_;
    int zb = blockIdx.z; int s = zb >> 3; int b = zb & 7;
    int t0 = s * CB_;
    int tid = threadIdx.x;
    int m0 = blockIdx.y * 128, n0 = blockIdx.x * 128;
    int warp = tid >> 5, lane = tid & 31;
    int warp_m = warp >> 1, warp_n = warp & 1;
    int g = lane >> 2, tq = lane & 3;
    int lrow = tid >> 1, lc = (tid & 1) * 2;
    float acc[2][8][4] = {};

    hloop(g_vTs + ((size_t)b*D_ + m0 + lrow)*T_ + t0 + lc*8,
          g_koutT + ((size_t)b*D_ + n0 + lrow)*T_ + t0 + lc*8,
          CB_ >> 5, 16, As, Bs, acc, warp_m, warp_n, lane, tid);

    __half* U = g_U + (size_t)(s * B_ + b) * DD_;
    #pragma unroll
    for (int mt = 0; mt < 2; mt++)
        #pragma unroll
        for (int h = 0; h < 2; h++) {
            int d = m0 + warp_m * 32 + mt * 16 + g + h * 8;
            #pragma unroll
            for (int nt = 0; nt < 8; nt++) {
                int e = n0 + warp_n * 64 + nt * 8 + tq * 2;
                *(__half2*)(U + (size_t)d * D_ + e) =
                    __floats2half2_rn(acc[mt][nt][h*2+0], acc[mt][nt][h*2+1]);
            }
        }
}

// ---------------- W prefix scan: Whs[s] = sum_{j<s} gC^{s-1-j} U_j ----------
// Each block owns an 8192-element flat slice; 32 fp32 per thread in registers.
__global__ void k_wscan() {
    int b = blockIdx.y;
    size_t off0 = (size_t)b * DD_ + (size_t)blockIdx.x * 8192;
    int tid = threadIdx.x;
    float gC = __expf((float)CB_ * g_consts[0]);
    float W[32] = {};
    for (int s = 0; s < NSTEP_; s++) {
        size_t so = (size_t)(s * B_) * DD_ + off0;
        #pragma unroll
        for (int k = 0; k < 4; k++) {
            size_t o = so + (size_t)k * 2048 + tid * 8;
            // store prefix (W before adding U_s)
            __half2 h0 = __floats2half2_rn(W[k*8+0], W[k*8+1]);
            __half2 h1 = __floats2half2_rn(W[k*8+2], W[k*8+3]);
            __half2 h2 = __floats2half2_rn(W[k*8+4], W[k*8+5]);
            __half2 h3 = __floats2half2_rn(W[k*8+6], W[k*8+7]);
            uint4 pack;
            pack.x = *(uint32_t*)&h0; pack.y = *(uint32_t*)&h1;
            pack.z = *(uint32_t*)&h2; pack.w = *(uint32_t*)&h3;
            *(uint4*)(g_Whs + o) = pack;
            // W = gC*W + U_s
            uint4 u = *(const uint4*)(g_U + o);
            __half2 u0 = *(__half2*)&u.x, u1 = *(__half2*)&u.y;
            __half2 u2 = *(__half2*)&u.z, u3 = *(__half2*)&u.w;
            float2 f0 = __half22float2(u0), f1 = __half22float2(u1);
            float2 f2 = __half22float2(u2), f3 = __half22float2(u3);
            W[k*8+0] = gC*W[k*8+0] + f0.x; W[k*8+1] = gC*W[k*8+1] + f0.y;
            W[k*8+2] = gC*W[k*8+2] + f1.x; W[k*8+3] = gC*W[k*8+3] + f1.y;
            W[k*8+4] = gC*W[k*8+4] + f2.x; W[k*8+5] = gC*W[k*8+5] + f2.y;
            W[k*8+6] = gC*W[k*8+6] + f3.x; W[k*8+7] = gC*W[k*8+7] + f3.y;
        }
    }
}

// ---------------- batched reads: inter + intra fused ------------------------
// reads[t0+i, d] = gamma^i * sum_e out[t0+i,e] Whs[s][d,e]  +  sum_j P[i,j] vT[d,j]
__global__ __launch_bounds__(256, 2) void k_readsall() {
    extern __shared__ __align__(16) __half sm16[];
    __half* As = sm16;
    __half* Bs = sm16 + NKST_ * STAGE_HALFS_;
    int zb = blockIdx.z; int s = zb >> 3; int b = zb & 7;
    int t0 = s * CB_;
    int tid = threadIdx.x;
    int m0 = blockIdx.y * 128, n0 = blockIdx.x * 128;   // m over CB, n over D
    int warp = tid >> 5, lane = tid & 31;
    int warp_m = warp >> 1, warp_n = warp & 1;
    int g = lane >> 2, tq = lane & 3;
    int lrow = tid >> 1, lc = (tid & 1) * 2;
    float lg = g_consts[0];
    float acc[2][8][4] = {};

    // phase 1: inter = out @ Whs[s]^T
    hloop(g_outh + ((size_t)b*T_ + t0 + m0 + lrow)*D_ + lc*8,
          g_Whs + (size_t)(s * B_ + b) * DD_ + (size_t)(n0 + lrow)*D_ + lc*8,
          D_ >> 5, 16, As, Bs, acc, warp_m, warp_n, lane, tid);

    // scale by gamma^i
    #pragma unroll
    for (int mt = 0; mt < 2; mt++)
        #pragma unroll
        for (int h = 0; h < 2; h++) {
            int mi = m0 + warp_m * 32 + mt * 16 + g + h * 8;
            float sc = __expf((float)mi * lg);
            #pragma unroll
            for (int nt = 0; nt < 8; nt++) {
                acc[mt][nt][h*2+0] *= sc;
                acc[mt][nt][h*2+1] *= sc;
            }
        }

    // phase 2: intra = P @ vT^T
    hloop(g_Ph + (size_t)(s * B_ + b) * CB_ * CB_ + (size_t)(m0 + lrow) * CB_ + lc*8,
          g_vT + ((size_t)b*D_ + n0 + lrow)*T_ + t0 + lc*8,
          CB_ >> 5, 16, As, Bs, acc, warp_m, warp_n, lane, tid);

    #pragma unroll
    for (int mt = 0; mt < 2; mt++)
        #pragma unroll
        for (int h = 0; h < 2; h++) {
            int mi = m0 + warp_m * 32 + mt * 16 + g + h * 8;
            size_t row = ((size_t)b * T_ + t0 + mi) * D_;
            #pragma unroll
            for (int nt = 0; nt < 8; nt++) {
                int ni = n0 + warp_n * 64 + nt * 8 + tq * 2;
                *(__half2*)(g_readsh + row + ni) =
                    __floats2half2_rn(acc[mt][nt][h*2+0], acc[mt][nt][h*2+1]);
            }
        }
}

// ---------------- launch ----------------------------------------------------
extern "C" void kernel_launch(void* const* d_in, const int* in_sizes, int n_in,
                              void* d_out, int out_size) {
    const float* x         = (const float*)d_in[0];
    const float* norm_w    = (const float*)d_in[1];
    const float* proj_w    = (const float*)d_in[2];
    const float* gate_w    = (const float*)d_in[3];
    const float* conv_w    = (const float*)d_in[4];
    const float* conv_b    = (const float*)d_in[5];
    const float* out_proj  = (const float*)d_in[6];
    const float* write_w   = (const float*)d_in[7];
    const float* read_w    = (const float*)d_in[8];
    const float* decay     = (const float*)d_in[9];
    const float* log_alpha = (const float*)d_in[10];
    float* out = (float*)d_out;

    float* p_out;
    __half *p_xnh, *p_valh, *p_gateh, *p_hh, *p_outh, *p_vh, *p_readsh, *p_wh;
    cudaGetSymbolAddress((void**)&p_out,    g_out);
    cudaGetSymbolAddress((void**)&p_xnh,    g_xnh);
    cudaGetSymbolAddress((void**)&p_valh,   g_valh);
    cudaGetSymbolAddress((void**)&p_gateh,  g_gateh);
    cudaGetSymbolAddress((void**)&p_hh,     g_hh);
    cudaGetSymbolAddress((void**)&p_outh,   g_outh);
    cudaGetSymbolAddress((void**)&p_vh,     g_vh);
    cudaGetSymbolAddress((void**)&p_readsh, g_readsh);
    cudaGetSymbolAddress((void**)&p_wh,     g_wh);
    __half* wh_proj  = p_wh;
    __half* wh_gate  = p_wh + 1179648;
    __half* wh_outp  = p_wh + 2359296;
    __half* wh_write = p_wh + 3538944;
    __half* wh_read  = p_wh + 4128768;

    static int smem_set = 0;
    if (!smem_set) {
        cudaFuncSetAttribute(k_hgemm16, cudaFuncAttributeMaxDynamicSharedMemorySize, GSM_);
        cudaFuncSetAttribute(k_pchunk,  cudaFuncAttributeMaxDynamicSharedMemorySize, GSM_);
        cudaFuncSetAttribute(k_updateU, cudaFuncAttributeMaxDynamicSharedMemorySize, GSM_);
        cudaFuncSetAttribute(k_readsall,cudaFuncAttributeMaxDynamicSharedMemorySize, GSM_);
        smem_set = 1;
    }

    k_consts<<<1, 1>>>(decay, log_alpha);
    k_h2<<<(DI_*D_/2+255)/256, 256>>>(proj_w,   wh_proj,  DI_*D_/2);
    k_h2<<<(DI_*D_/2+255)/256, 256>>>(gate_w,   wh_gate,  DI_*D_/2);
    k_h2<<<(DI_*D_/2+255)/256, 256>>>(out_proj, wh_outp,  D_*DI_/2);
    k_h2<<<(D_*D_/2+255)/256,  256>>>(write_w,  wh_write, D_*D_/2);
    k_h2<<<(D_*D_/2+255)/256,  256>>>(read_w,   wh_read,  D_*D_/2);
    k_xnorm<<<M_/8, 256>>>(x, norm_w);

    // val(fp16) = xn @ proj^T ; gate(fp16) = silu(xn @ gate^T)
    k_hgemm16<<<dim3(DI_/128, M_/128), 256, GSM_>>>(
        p_xnh, wh_proj, nullptr, p_valh, DI_, D_, 0, nullptr, nullptr);
    k_hgemm16<<<dim3(DI_/128, M_/128), 256, GSM_>>>(
        p_xnh, wh_gate, nullptr, p_gateh, DI_, D_, 1, nullptr, nullptr);
    // h(fp16) = silu(conv(val)+b) * gate
    k_conv<<<dim3(DI_/256, T_/8, B_), 256>>>(conv_w, conv_b);
    // out = h @ out_proj^T  (fp32 + fp16)
    k_hgemm16<<<dim3(D_/128, M_/128), 256, GSM_>>>(
        p_hh, wh_outp, p_out, p_outh, D_, DI_, 0, nullptr, nullptr);
    // v(fp16) = out @ write^T
    k_hgemm16<<<dim3(D_/128, M_/128), 256, GSM_>>>(
        p_outh, wh_write, nullptr, p_vh, D_, D_, 0, nullptr, nullptr);

    // transposed fp16 operand copies
    k_transV<<<dim3(T_/32, D_/32, B_), 256>>>();
    k_transK<<<dim3(T_/32, D_/32, B_), 256>>>();

    // fully-parallel chunk work
    k_pchunk <<<dim3(CB_/128, CB_/128, NSTEP_*B_), 256, GSM_>>>();
    k_updateU<<<dim3(D_/128,  D_/128,  NSTEP_*B_), 256, GSM_>>>();

    // prefix scan of W snapshots (parallel over tiles; sequential over s in-regs)
    k_wscan<<<dim3((int)(DD_/8192), B_), 256>>>();

    // fused inter+intra reads (one wide launch)
    k_readsall<<<dim3(D_/128, CB_/128, NSTEP_*B_), 256, GSM_>>>();

    // final: y = x + out + alpha * (reads @ read^T)
    k_hgemm16<<<dim3(D_/128, M_/128), 256, GSM_>>>(
        p_readsh, wh_read, out, nullptr, D_, D_, 2, x, p_out);
}